// round 14
// baseline (speedup 1.0000x reference)
#include <cuda_runtime.h>
#include <cuda_fp16.h>
#include <cstdint>

#define NMP     3
#define NNODES  50000
#define D       128
#define E       32
#define DEG     32
#define NEDGE   200000
#define BB      1024
#define S       16
#define NC      8
#define M1      (BB*S)      /* 16384 */
#define DE      (D+E)       /* 160 */

#define NSTG    18          /* 288 / 16 k-stages */
#define ASLAB   2560        /* fp32 slab for edge pack: 128 rows * 20 floats */
#define KPA     24          /* fp16 A smem stride (halves), 48B rows */
#define H16SLAB (128*KPA)   /* 3072 halves = 6144B per k16 stage */
#define EBSLAB  640         /* 16 k * 40 floats (32 data + 8 pad)   */

// ---------------- scratch (static device globals; no runtime alloc) ----------------
__device__ int    g_nb1 [NMP*M1];
__device__ int    g_eid1[NMP*M1];
__device__ float  g_nin1[NMP*BB*DE];
__device__ float  g_h0  [NMP*BB*D];
__device__ float  g_ninL1[NMP*BB*DE];
__device__ float  g_outs[NMP*BB*D];
__device__ __half g_feats16[(size_t)NNODES*D];              // fp16 feats table (12.8MB)
__device__ __half g_edge16[(size_t)NMP*NEDGE*E];            // fp16 edge table (38.4MB)
__device__ __half g_a1pk16[(size_t)NMP*128*NSTG*H16SLAB];   // fp16 packed A (42.5MB)
__device__ float  g_epk[(size_t)NMP*128*10*ASLAB];
__device__ __half g_Whpk16[NMP*2*NSTG*H16SLAB];             // fp16 packed Wh, n-major
__device__ float  g_Wepk[NMP*2*NSTG*EBSLAB];

// ---------------- helpers ----------------
__device__ __forceinline__ float tf32r(float x) {
    uint32_t u; asm("cvt.rna.tf32.f32 %0, %1;" : "=r"(u) : "f"(x));
    return __uint_as_float(u);
}
__device__ __forceinline__ uint32_t fu(float x) { return __float_as_uint(x); }
__device__ __forceinline__ uint32_t sptr(const void* p) {
    return (uint32_t)__cvta_generic_to_shared(p);
}
__device__ __forceinline__ void ldsm_x4(uint32_t& d0, uint32_t& d1, uint32_t& d2, uint32_t& d3,
                                        uint32_t a) {
    asm volatile("ldmatrix.sync.aligned.m8n8.x4.shared.b16 {%0,%1,%2,%3}, [%4];"
        : "=r"(d0), "=r"(d1), "=r"(d2), "=r"(d3) : "r"(a));
}
__device__ __forceinline__ uint32_t cvt_frag(uint32_t v) {
    return fu(tf32r(__uint_as_float(v)));
}
__device__ __forceinline__ float wred(float v) {
    #pragma unroll
    for (int o = 16; o; o >>= 1) v += __shfl_xor_sync(0xffffffffu, v, o);
    return v;
}
__device__ __forceinline__ uint32_t h2pack(float a, float b) {
    __half2 h = __floats2half2_rn(a, b);
    return *(uint32_t*)&h;
}
__device__ __forceinline__ void acc_h4(float4& a, uint2 hv) {
    float2 f0 = __half22float2(*(__half2*)&hv.x);
    float2 f1 = __half22float2(*(__half2*)&hv.y);
    a.x += f0.x; a.y += f0.y; a.z += f1.x; a.w += f1.y;
}

#define MMA_TF32(c, a, b) \
    asm volatile("mma.sync.aligned.m16n8k8.row.col.f32.tf32.tf32.f32 " \
        "{%0,%1,%2,%3}, {%4,%5,%6,%7}, {%8,%9}, {%0,%1,%2,%3};" \
        : "+f"((c)[0]), "+f"((c)[1]), "+f"((c)[2]), "+f"((c)[3]) \
        : "r"((a)[0]), "r"((a)[1]), "r"((a)[2]), "r"((a)[3]), \
          "r"((b)[0]), "r"((b)[1]))

#define MMA_F16(c, a, b) \
    asm volatile("mma.sync.aligned.m16n8k16.row.col.f32.f16.f16.f32 " \
        "{%0,%1,%2,%3}, {%4,%5,%6,%7}, {%8,%9}, {%0,%1,%2,%3};" \
        : "+f"((c)[0]), "+f"((c)[1]), "+f"((c)[2]), "+f"((c)[3]) \
        : "r"((a)[0]), "r"((a)[1]), "r"((a)[2]), "r"((a)[3]), \
          "r"((b)[0]), "r"((b)[1]))

#define MBAR_INIT(addr, cnt) \
    asm volatile("mbarrier.init.shared.b64 [%0], %1;" :: "r"(addr), "r"(cnt) : "memory")
#define MBAR_EXPECT_TX(addr, bytes) \
    asm volatile("mbarrier.arrive.expect_tx.shared.b64 _, [%0], %1;" :: "r"(addr), "r"(bytes) : "memory")
#define MBAR_ARRIVE(addr) \
    asm volatile("mbarrier.arrive.shared.b64 _, [%0];" :: "r"(addr) : "memory")
#define MBAR_WAIT(addr, parity) do {                                            \
    uint32_t _m = (addr); uint32_t _p = (parity); uint32_t _done;               \
    asm volatile("{\n\t.reg .pred p;\n\t"                                       \
        "mbarrier.try_wait.parity.acquire.cta.shared::cta.b64 p, [%1], %2;\n\t" \
        "selp.b32 %0, 1, 0, p;\n\t}"                                            \
        : "=r"(_done) : "r"(_m), "r"(_p) : "memory");                           \
    if (!_done) {                                                               \
        asm volatile("{\n\t.reg .pred P1;\n\t"                                  \
            "WL_%=:\n\t"                                                        \
            "mbarrier.try_wait.parity.acquire.cta.shared::cta.b64 P1, [%0], %1, 0x989680;\n\t" \
            "@P1 bra.uni WD_%=;\n\t"                                            \
            "bra.uni WL_%=;\n\t"                                                \
            "WD_%=:\n\t}"                                                       \
            :: "r"(_m), "r"(_p) : "memory");                                    \
    }                                                                           \
} while (0)
#define BULK_CP(dst, src, bytes, mbar) \
    asm volatile("cp.async.bulk.shared::cta.global.mbarrier::complete_tx::bytes [%0], [%1], %2, [%3];" \
        :: "r"(dst), "l"(src), "r"(bytes), "r"(mbar) : "memory")

// ---------------- -1) fp16 table conversion ----------------
__global__ void k_cvt(const float* __restrict__ feats,
                      const float* __restrict__ edge_emb) {
    int t = blockIdx.x * blockDim.x + threadIdx.x;
    if (t < NNODES * D / 4) {
        float4 v = ((const float4*)feats)[t];
        uint2 pk; pk.x = h2pack(v.x, v.y); pk.y = h2pack(v.z, v.w);
        *(uint2*)&g_feats16[(size_t)t * 4] = pk;
    }
    if (t < NMP * NEDGE * E / 4) {
        float4 v = ((const float4*)edge_emb)[t];
        uint2 pk; pk.x = h2pack(v.x, v.y); pk.y = h2pack(v.z, v.w);
        *(uint2*)&g_edge16[(size_t)t * 4] = pk;
    }
}

// ---------------- 0) merged prefix: fp16 weight pack + edge weight pack + hop-1 ids ----------------
__global__ void k_prep0(const int* __restrict__ ids,
                        const int* __restrict__ adj_nodes,
                        const int* __restrict__ adj_edges,
                        const float* __restrict__ W_self,
                        const float* __restrict__ W_neigh,
                        const float* __restrict__ W_edge) {
    int t = blockIdx.x * blockDim.x + threadIdx.x;
    if (t < NMP*2*288*128) {
        int wl = t / (288*128);
        int r  = t % (288*128);
        int k  = r / 128, n = r % 128;
        float v = (k < 128) ? W_self [wl*128*128 + k*128 + n]
                            : W_neigh[wl*160*128 + (k-128)*128 + n];
        g_Whpk16[(size_t)(wl*NSTG + (k>>4))*H16SLAB + n*KPA + (k&15)] = __float2half(v);
    }
    if (t < NMP*2*288*32) {
        int wl = t / (288*32);
        int r  = t % (288*32);
        int k  = r / 32, n = r % 32;
        g_Wepk[(size_t)(wl*NSTG + (k>>4))*EBSLAB + (k&15)*40 + n] = tf32r(W_edge[t]);
    }
    if (t < NMP * M1) {
        int mp = t / M1;
        int r  = t % M1;
        int b  = r >> 4;
        int s  = r & 15;
        long base = ((long)mp * NNODES + ids[b]) * DEG + s;
        g_nb1[t]  = adj_nodes[base];
        g_eid1[t] = adj_edges[base];
    }
}

// ---------------- 2) hop-2 gather (fp16 tables) + mean + fp16 A-pack ----------------
__global__ void k_mean_hop2(const int* __restrict__ adj_nodes,
                            const int* __restrict__ adj_edges) {
    int w    = (blockIdx.x * blockDim.x + threadIdx.x) >> 5;
    int lane = threadIdx.x & 31;
    if (w >= NMP * M1) return;
    int mp = w / M1;
    int m  = w % M1;
    int nb1 = g_nb1[w];
    long abase = ((long)mp * NNODES + nb1) * DEG;
    const int* an = adj_nodes + abase;
    const int* ae = adj_edges + abase;
    float4 aF = make_float4(0.f,0.f,0.f,0.f);
    float4 aE = make_float4(0.f,0.f,0.f,0.f);
    #pragma unroll
    for (int s = 0; s < S; s++) {
        int nb = an[s];
        uint2 hv = *(const uint2*)&g_feats16[(size_t)nb * D + lane * 4];
        acc_h4(aF, hv);
        if (lane < E/4) {
            int e = ae[s];
            uint2 ev = *(const uint2*)&g_edge16[((size_t)mp * NEDGE + e) * E + lane * 4];
            acc_h4(aE, ev);
        }
    }
    const float inv = 1.0f / S;
    int blk = m >> 7, r = m & 127;
    size_t pb = (size_t)(mp * 128 + blk) * NSTG;
    int sq = lane >> 2, o = (lane & 3) * 4;
    // feats[nb1] copy: raw fp16 passthrough
    uint2 fv = *(const uint2*)&g_feats16[(size_t)nb1 * D + lane * 4];
    *(uint2*)&g_a1pk16[(pb + sq) * H16SLAB + r * KPA + o] = fv;
    {
        uint2 pk; pk.x = h2pack(aF.x*inv, aF.y*inv); pk.y = h2pack(aF.z*inv, aF.w*inv);
        *(uint2*)&g_a1pk16[(pb + 8 + sq) * H16SLAB + r * KPA + o] = pk;
    }
    if (lane < E/4) {
        uint2 pk; pk.x = h2pack(aE.x*inv, aE.y*inv); pk.y = h2pack(aE.z*inv, aE.w*inv);
        *(uint2*)&g_a1pk16[(pb + 16 + sq) * H16SLAB + r * KPA + o] = pk;
    }
}

// ---------------- 3) hop-1 gather (fp16 tables) + mean -> nin1 ----------------
__global__ void k_mean_hop1() {
    int w    = (blockIdx.x * blockDim.x + threadIdx.x) >> 5;
    int lane = threadIdx.x & 31;
    if (w >= NMP * BB) return;
    int mp = w / BB;
    int b  = w % BB;
    int base = mp * M1 + b * S;
    float4 aF = make_float4(0.f,0.f,0.f,0.f);
    float4 aE = make_float4(0.f,0.f,0.f,0.f);
    #pragma unroll
    for (int s = 0; s < S; s++) {
        int nb = g_nb1[base + s];
        uint2 hv = *(const uint2*)&g_feats16[(size_t)nb * D + lane * 4];
        acc_h4(aF, hv);
        if (lane < E/4) {
            int e = g_eid1[base + s];
            uint2 ev = *(const uint2*)&g_edge16[((size_t)mp * NEDGE + e) * E + lane * 4];
            acc_h4(aE, ev);
        }
    }
    const float inv = 1.0f / S;
    float4* o = (float4*)(g_nin1 + (size_t)w * DE);
    o[lane] = make_float4(aF.x*inv, aF.y*inv, aF.z*inv, aF.w*inv);
    if (lane < E/4)
        o[D/4 + lane] = make_float4(aE.x*inv, aE.y*inv, aE.z*inv, aE.w*inv);
}

// ---------------- 3b) pack ee1 gather (fp16 table) -> g_epk slabs 8..9 ----------------
__global__ void k_pack_e() {
    int w    = (blockIdx.x * blockDim.x + threadIdx.x) >> 5;
    int lane = threadIdx.x & 31;
    if (w >= NMP * M1) return;
    int mp = w / M1;
    int m  = w % M1;
    int e  = g_eid1[w];
    float v = __half2float(g_edge16[((size_t)mp * NEDGE + e) * E + lane]);
    int blk = m >> 7, r = m & 127;
    g_epk[((size_t)(mp*128 + blk)*10 + 8 + (lane >> 4)) * ASLAB + r*20 + (lane & 15)] = v;
}

// ---------------- gemm_h0: fp16 HMMA (m16n8k16) + bulk-DMA, NS=4 ----------------
__global__ __launch_bounds__(256) void gemm_h0() {
    constexpr int NS = 4;
    constexpr uint32_t STG_BYTES = 2 * H16SLAB * 2;
    extern __shared__ __half hsm[];
    __shared__ __align__(8) uint64_t mbar[2 * NS];

    int mp  = blockIdx.y;
    int blk = blockIdx.x;
    int m0  = blk * 128;
    int tid  = threadIdx.x;
    int lane = tid & 31;
    int w    = tid >> 5;
    int wm   = w >> 2;
    int wn   = w & 3;
    uint32_t lmoff = (uint32_t)((lane & 15) * KPA * 2 + (lane >> 4) * 16);

    uint32_t full0  = sptr(&mbar[0]);
    uint32_t empty0 = sptr(&mbar[NS]);

    if (tid == 0) {
        #pragma unroll
        for (int s = 0; s < NS; s++) {
            MBAR_INIT(full0  + s * 8, 1);
            MBAR_INIT(empty0 + s * 8, 256);
        }
    }
    __syncthreads();

    const __half* Asrc = g_a1pk16 + (size_t)(mp * 128 + blk) * NSTG * H16SLAB;
    const __half* Bsrc = g_Whpk16 + (size_t)(mp * 2 + 0) * NSTG * H16SLAB;
    uint32_t smem0 = sptr(hsm);

    if (tid == 0) {
        #pragma unroll
        for (int t = 0; t < NS - 1; t++) {
            uint32_t fb = full0 + t * 8;
            uint32_t sa = smem0 + t * STG_BYTES;
            MBAR_EXPECT_TX(fb, STG_BYTES);
            BULK_CP(sa,               Asrc + (size_t)t * H16SLAB, H16SLAB * 2, fb);
            BULK_CP(sa + H16SLAB * 2, Bsrc + (size_t)t * H16SLAB, H16SLAB * 2, fb);
        }
    }

    float acc[4][4][4];
    #pragma unroll
    for (int i = 0; i < 4; i++)
        #pragma unroll
        for (int j = 0; j < 4; j++)
            #pragma unroll
            for (int q = 0; q < 4; q++) acc[i][j][q] = 0.f;

    int cslot = 0, cph = 0;
    int pslot = NS - 1, pph = 1;

    for (int s = 0; s < NSTG; s++) {
        if (tid == 0) {
            int t = s + NS - 1;
            if (t < NSTG) {
                MBAR_WAIT(empty0 + pslot * 8, pph);
                uint32_t fb = full0 + pslot * 8;
                uint32_t sa = smem0 + pslot * STG_BYTES;
                MBAR_EXPECT_TX(fb, STG_BYTES);
                BULK_CP(sa,               Asrc + (size_t)t * H16SLAB, H16SLAB * 2, fb);
                BULK_CP(sa + H16SLAB * 2, Bsrc + (size_t)t * H16SLAB, H16SLAB * 2, fb);
                if (++pslot == NS) { pslot = 0; pph ^= 1; }
            }
        }
        MBAR_WAIT(full0 + cslot * 8, cph);

        __half* As = hsm + cslot * 2 * H16SLAB;
        __half* Bs = As + H16SLAB;
        uint32_t as_base = sptr(As);
        uint32_t afr[4][4], bfr[4][2];
        #pragma unroll
        for (int mt = 0; mt < 4; mt++) {
            uint32_t ad = as_base + (uint32_t)((wm * 64 + mt * 16) * KPA * 2) + lmoff;
            ldsm_x4(afr[mt][0], afr[mt][1], afr[mt][2], afr[mt][3], ad);
        }
        #pragma unroll
        for (int nt = 0; nt < 4; nt++) {
            int n = wn * 32 + nt * 8 + (lane >> 2);
            const uint32_t* bp = (const uint32_t*)(Bs + n * KPA);
            bfr[nt][0] = bp[lane & 3];
            bfr[nt][1] = bp[4 + (lane & 3)];
        }
        #pragma unroll
        for (int mt = 0; mt < 4; mt++)
            #pragma unroll
            for (int nt = 0; nt < 4; nt++)
                MMA_F16(acc[mt][nt], afr[mt], bfr[nt]);

        MBAR_ARRIVE(empty0 + cslot * 8);
        if (++cslot == NS) { cslot = 0; cph ^= 1; }
    }

    #pragma unroll
    for (int mt = 0; mt < 4; mt++)
        #pragma unroll
        for (int nt = 0; nt < 4; nt++)
            #pragma unroll
            for (int q = 0; q < 4; q++)
                acc[mt][nt][q] = fmaxf(acc[mt][nt][q], 0.f);

    float* epb = g_epk + (size_t)(mp * 128 + blk) * 10 * ASLAB;
    int q8 = lane >> 2, c4 = lane & 3;
    #pragma unroll
    for (int mt = 0; mt < 4; mt++) {
        int r = wm * 64 + mt * 16 + q8;
        #pragma unroll
        for (int nt = 0; nt < 4; nt++) {
            int slab = wn * 2 + (nt >> 1);
            int ci   = (nt & 1) * 8 + 2 * c4;
            *(float2*)&epb[(size_t)slab * ASLAB + r       * 20 + ci] = make_float2(acc[mt][nt][0], acc[mt][nt][1]);
            *(float2*)&epb[(size_t)slab * ASLAB + (r + 8) * 20 + ci] = make_float2(acc[mt][nt][2], acc[mt][nt][3]);
        }
    }

    const float inv16 = 1.0f / 16.0f;
    #pragma unroll
    for (int mt = 0; mt < 4; mt++) {
        int b = (m0 + wm * 64 + mt * 16) >> 4;
        float* dst = g_ninL1 + ((size_t)mp * BB + b) * DE;
        #pragma unroll
        for (int nt = 0; nt < 4; nt++) {
            float s0 = acc[mt][nt][0] + acc[mt][nt][2];
            float s1 = acc[mt][nt][1] + acc[mt][nt][3];
            #pragma unroll
            for (int o = 4; o < 32; o <<= 1) {
                s0 += __shfl_xor_sync(0xffffffffu, s0, o);
                s1 += __shfl_xor_sync(0xffffffffu, s1, o);
            }
            if (lane < 4) {
                int c = wn * 32 + nt * 8 + 2 * lane;
                *(float2*)(dst + c) = make_float2(s0 * inv16, s1 * inv16);
            }
        }
    }
}

// ---------------- gemm_edge: bulk-DMA staged TF32; mean(relu(.)) -> ninL1[:, D:] ----------------
__global__ __launch_bounds__(256) void gemm_edge() {
    constexpr int NS   = 3;
    constexpr int SLOT = ASLAB + EBSLAB;
    __shared__ float ring[NS * SLOT];
    __shared__ float h0t[8 * 128];
    __shared__ __align__(8) uint64_t mbar[2 * NS + 1];

    int mp  = blockIdx.y;
    int blk = blockIdx.x;
    int m0  = blk * 128;
    int tid  = threadIdx.x;
    int lane = tid & 31;
    int w    = tid >> 5;
    int q    = lane >> 2;
    int c4   = lane & 3;
    int row16 = lane & 15;
    int sel4  = (lane >> 4) * 4;
    uint32_t lmoff = (uint32_t)((row16 * 20 + sel4) * 4);

    uint32_t full0  = sptr(&mbar[0]);
    uint32_t empty0 = sptr(&mbar[NS]);
    uint32_t h0bar  = sptr(&mbar[2 * NS]);

    if (tid == 0) {
        #pragma unroll
        for (int s = 0; s < NS; s++) {
            MBAR_INIT(full0  + s * 8, 1);
            MBAR_INIT(empty0 + s * 8, 256);
        }
        MBAR_INIT(h0bar, 1);
    }
    __syncthreads();

    const float* Apk = g_epk  + (size_t)(mp * 128 + blk) * 10 * ASLAB;
    const float* Bpk = g_Wepk + (size_t)(mp * 2 + 0) * NSTG * EBSLAB;
    const float* H0s = g_h0 + ((size_t)mp * BB + (m0 >> 4)) * D;
    uint32_t ring0 = sptr(ring);

#define ISSUE_EDGE(T, SLOTI) do {                                               \
    int _t = (T);                                                               \
    uint32_t fb = full0 + (SLOTI) * 8;                                          \
    uint32_t sa = ring0 + (SLOTI) * SLOT * 4;                                   \
    uint32_t bytes = EBSLAB * 4 + ((_t >= 8) ? ASLAB * 4 : 0);                  \
    MBAR_EXPECT_TX(fb, bytes);                                                  \
    if (_t >= 8)                                                                \
        BULK_CP(sa, Apk + (size_t)(_t - 8) * ASLAB, ASLAB * 4, fb);             \
    BULK_CP(sa + ASLAB * 4, Bpk + (size_t)_t * EBSLAB, EBSLAB * 4, fb);         \
} while (0)

    if (tid == 0) {
        MBAR_EXPECT_TX(h0bar, 8 * 128 * 4);
        BULK_CP(sptr(h0t), H0s, 8 * 128 * 4, h0bar);
        #pragma unroll
        for (int t = 0; t < NS - 1; t++) ISSUE_EDGE(t, t);
    }
    MBAR_WAIT(h0bar, 0);

    float acc[4][4];
    #pragma unroll
    for (int j = 0; j < 4; j++)
        #pragma unroll
        for (int t = 0; t < 4; t++) acc[j][t] = 0.f;

    int cslot = 0, cph = 0;
    int pslot = NS - 1, pph = 1;

    for (int s = 0; s < NSTG; s++) {
        if (tid == 0) {
            int t = s + NS - 1;
            if (t < NSTG) {
                MBAR_WAIT(empty0 + pslot * 8, pph);
                ISSUE_EDGE(t, pslot);
                if (++pslot == NS) { pslot = 0; pph ^= 1; }
            }
        }
        MBAR_WAIT(full0 + cslot * 8, cph);

        float* As = ring + cslot * SLOT;
        float* Bs = As + ASLAB;
        uint32_t as_base = sptr(As);
        #pragma unroll
        for (int kk = 0; kk < 16; kk += 8) {
            uint32_t afr[4], bfr[4][2];
            if (s < 8) {
                int kb = s * 16 + kk;
                uint32_t v0 = fu(tf32r(h0t[w * 128 + kb + c4]));
                uint32_t v1 = fu(tf32r(h0t[w * 128 + kb + c4 + 4]));
                afr[0] = v0; afr[1] = v0; afr[2] = v1; afr[3] = v1;
            } else {
                uint32_t ad = as_base + (uint32_t)(((w * 16) * 20 + kk) * 4) + lmoff;
                ldsm_x4(afr[0], afr[1], afr[2], afr[3], ad);
                afr[0] = cvt_frag(afr[0]);
                afr[1] = cvt_frag(afr[1]);
                afr[2] = cvt_frag(afr[2]);
                afr[3] = cvt_frag(afr[3]);
            }
            #pragma unroll
            for (int nt = 0; nt < 4; nt++) {
                int cN = nt * 8 + q;
                bfr[nt][0] = fu(Bs[(kk     + c4) * 40 + cN]);
                bfr[nt][1] = fu(Bs[(kk + 4 + c4) * 40 + cN]);
            }
            #pragma unroll
            for (int nt = 0; nt < 4; nt++)
                MMA_TF32(acc[nt], afr, bfr[nt]);
        }

        MBAR_ARRIVE(empty0 + cslot * 8);
        if (++cslot == NS) { cslot = 0; cph ^= 1; }
    }
#undef ISSUE_EDGE

    const float inv16 = 1.0f / 16.0f;
    int b = (m0 >> 4) + w;
    float* dst = g_ninL1 + ((size_t)mp * BB + b) * DE + D;
    #pragma unroll
    for (int nt = 0; nt < 4; nt++) {
        float s0 = fmaxf(acc[nt][0], 0.f) + fmaxf(acc[nt][2], 0.f);
        float s1 = fmaxf(acc[nt][1], 0.f) + fmaxf(acc[nt][3], 0.f);
        #pragma unroll
        for (int o = 4; o < 32; o <<= 1) {
            s0 += __shfl_xor_sync(0xffffffffu, s0, o);
            s1 += __shfl_xor_sync(0xffffffffu, s1, o);
        }
        if (lane < 4) {
            int c = nt * 8 + 2 * lane;
            *(float2*)(dst + c) = make_float2(s0 * inv16, s1 * inv16);
        }
    }
}

// ---------------- small node GEMM (cp.async/ldmatrix path), M=1024 ----------------
template<int MODE>
__global__ __launch_bounds__(256) void gemm_h_small(const float* __restrict__ feats,
                                                    const int*   __restrict__ ids,
                                                    const float* __restrict__ W_self,
                                                    const float* __restrict__ W_neigh,
                                                    int l) {
    constexpr int KTOT = D + DE;
    constexpr int NSG  = KTOT / 16;
    int mp = blockIdx.y;
    int m0 = blockIdx.x * 128;

    __shared__ float As[2][128][20];
    __shared__ float Bs[2][16][136];
    __shared__ const float* rowp[128];

    int tid  = threadIdx.x;
    int lane = tid & 31;
    int w    = tid >> 5;
    int wm   = w >> 2;
    int wn   = w & 3;
    int ar   = tid >> 1;
    int kq   = (tid & 1) * 8;
    int bk   = tid >> 4;
    int bn   = (tid & 15) * 8;
    int row16 = lane & 15;
    int sel4  = (lane >> 4) * 4;
    uint32_t lmoff = (uint32_t)((row16 * 20 + sel4) * 4);

    const float* P2 = (MODE == 1) ? g_nin1 : g_ninL1;
    float* Out      = (MODE == 1) ? g_h0   : g_outs;

    if (tid < 128) {
        int m = m0 + tid;
        rowp[tid] = (MODE == 1) ? (feats + (long)ids[m] * D)
                                : (g_h0 + ((long)mp * BB + m) * D);
    }
    __syncthreads();

    const float* Wsp = W_self  + ((long)(mp * 2 + l)) * D  * D;
    const float* Wnp = W_neigh + ((long)(mp * 2 + l)) * DE * D;
    const float* P2p = P2 + ((size_t)mp * BB + m0) * DE;

    float acc[4][4][4];
    #pragma unroll
    for (int i = 0; i < 4; i++)
        #pragma unroll
        for (int j = 0; j < 4; j++)
            #pragma unroll
            for (int q = 0; q < 4; q++) acc[i][j][q] = 0.f;

    float4 ra0, ra1, rb0, rb1;
#define LDG_H(K0) do {                                                          \
    int _k = (K0);                                                              \
    const float* ap = (_k < D) ? rowp[ar] + _k                                  \
                               : P2p + (long)ar * DE + (_k - D);                \
    ra0 = *(const float4*)(ap + kq);                                            \
    ra1 = *(const float4*)(ap + kq + 4);                                        \
    const float* wrow = (_k < D) ? (Wsp + (long)(_k + bk) * D)                  \
                                 : (Wnp + (long)(_k - D + bk) * D);             \
    rb0 = *(const float4*)(wrow + bn);                                          \
    rb1 = *(const float4*)(wrow + bn + 4);                                      \
} while (0)
#define STS_H(BUF) do {                                                         \
    As[BUF][ar][kq+0] = tf32r(ra0.x); As[BUF][ar][kq+1] = tf32r(ra0.y);         \
    As[BUF][ar][kq+2] = tf32r(ra0.z); As[BUF][ar][kq+3] = tf32r(ra0.w);         \
    As[BUF][ar][kq+4] = tf32r(ra1.x); As[BUF][ar][kq+5] = tf32r(ra1.y);         \
    As[BUF][ar][kq+6] = tf32r(ra1.z); As[BUF][ar][kq+7] = tf32r(ra1.w);         \
    Bs[BUF][bk][bn+0] = tf32r(rb0.x); Bs[BUF][bk][bn+1] = tf32r(rb0.y);         \
    Bs[BUF][bk][bn+2] = tf32r(rb0.z); Bs[BUF][bk][bn+3] = tf32r(rb0.w);         \
    Bs[BUF][bk][bn+4] = tf32r(rb1.x); Bs[BUF][bk][bn+5] = tf32r(rb1.y);         \
    Bs[BUF][bk][bn+6] = tf32r(rb1.z); Bs[BUF][bk][bn+7] = tf32r(rb1.w);         \
} while (0)

    LDG_H(0);
    STS_H(0);
    __syncthreads();

    for (int it = 0; it < NSG; ++it) {
        int cur = it & 1;
        if (it + 1 < NSG) LDG_H((it + 1) * 16);

        uint32_t as_base = sptr(&As[cur][0][0]);
        #pragma unroll
        for (int kk = 0; kk < 16; kk += 8) {
            uint32_t afr[4][4], bfr[4][2];
            #pragma unroll
            for (int mt = 0; mt < 4; mt++) {
                uint32_t ad = as_base + (uint32_t)(((wm * 64 + mt * 16) * 20 + kk) * 4) + lmoff;
                ldsm_x4(afr[mt][0], afr[mt][1], afr[mt][2], afr[mt][3], ad);
            }
            #pragma unroll
            for (int nt = 0; nt < 4; nt++) {
                int cN = wn * 32 + nt * 8 + (lane >> 2);
                bfr[nt][0] = fu(Bs[cur][kk     + (lane & 3)][cN]);
                bfr[nt][1] = fu(Bs[cur][kk + 4 + (lane & 3)][cN]);
            }
            #pragma unroll
            for (int mt = 0; mt < 4; mt++)
                #pragma unroll
                for (int nt = 0; nt < 4; nt++)
                    MMA_TF32(acc[mt][nt], afr[mt], bfr[nt]);
        }
        if (it + 1 < NSG) { STS_H(cur ^ 1); __syncthreads(); }
    }
#undef LDG_H
#undef STS_H

    size_t ob = ((size_t)mp * BB + m0) * D;
    #pragma unroll
    for (int mt = 0; mt < 4; mt++) {
        int r = wm * 64 + mt * 16 + (lane >> 2);
        #pragma unroll
        for (int nt = 0; nt < 4; nt++) {
            int c = wn * 32 + nt * 8 + 2 * (lane & 3);
            float2 v0, v1;
            v0.x = fmaxf(acc[mt][nt][0], 0.f); v0.y = fmaxf(acc[mt][nt][1], 0.f);
            v1.x = fmaxf(acc[mt][nt][2], 0.f); v1.y = fmaxf(acc[mt][nt][3], 0.f);
            *(float2*)(Out + ob + (size_t)r       * D + c) = v0;
            *(float2*)(Out + ob + (size_t)(r + 8) * D + c) = v1;
        }
    }
}

// ---------------- final fuse: warp-per-row, shuffle-only reductions ----------------
__global__ __launch_bounds__(256) void k_fuse(const float* __restrict__ attn,
                                              const float* __restrict__ fc_w,
                                              const float* __restrict__ fc_b,
                                              float* __restrict__ out) {
    __shared__ float sfw[D * NC];
    int tid = threadIdx.x;
    for (int i = tid; i < D * NC; i += 256) sfw[i] = fc_w[i];
    __syncthreads();

    int warp = tid >> 5, lane = tid & 31;
    int b = blockIdx.x * 8 + warp;
    int d0 = lane * 4;

    float4 v0 = *(const float4*)&g_outs[((size_t)0 * BB + b) * D + d0];
    float4 v1 = *(const float4*)&g_outs[((size_t)1 * BB + b) * D + d0];
    float4 v2 = *(const float4*)&g_outs[((size_t)2 * BB + b) * D + d0];
    float4 a  = *(const float4*)&attn[d0];

    float s0 = wred(v0.x*a.x + v0.y*a.y + v0.z*a.z + v0.w*a.w);
    float s1 = wred(v1.x*a.x + v1.y*a.y + v1.z*a.z + v1.w*a.w);
    float s2 = wred(v2.x*a.x + v2.y*a.y + v2.z*a.z + v2.w*a.w);
    s0 = tanhf(s0); s1 = tanhf(s1); s2 = tanhf(s2);
    float mx = fmaxf(s0, fmaxf(s1, s2));
    float e0 = expf(s0 - mx), e1 = expf(s1 - mx), e2 = expf(s2 - mx);
    float inv = 1.f / (e0 + e1 + e2);

    float em[4];
    em[0] = (e0*v0.x + e1*v1.x + e2*v2.x) * inv;
    em[1] = (e0*v0.y + e1*v1.y + e2*v2.y) * inv;
    em[2] = (e0*v0.z + e1*v1.z + e2*v2.z) * inv;
    em[3] = (e0*v0.w + e1*v1.w + e2*v2.w) * inv;

    float n2 = wred(em[0]*em[0] + em[1]*em[1] + em[2]*em[2] + em[3]*em[3]);
    float rn = 1.f / fmaxf(sqrtf(n2), 1e-12f);
    em[0] *= rn; em[1] *= rn; em[2] *= rn; em[3] *= rn;

    #pragma unroll
    for (int nc = 0; nc < NC; nc++) {
        float p = em[0] * sfw[(d0+0)*NC + nc] + em[1] * sfw[(d0+1)*NC + nc]
                + em[2] * sfw[(d0+2)*NC + nc] + em[3] * sfw[(d0+3)*NC + nc];
        p = wred(p);
        if (lane == 0) out[b * NC + nc] = p + fc_b[nc];
    }
}

// ---------------- launch ----------------
extern "C" void kernel_launch(void* const* d_in, const int* in_sizes, int n_in,
                              void* d_out, int out_size) {
    (void)in_sizes; (void)n_in; (void)out_size;
    const int*   ids       = (const int*)  d_in[0];
    const float* feats     = (const float*)d_in[1];
    const float* edge_emb  = (const float*)d_in[2];
    const int*   adj_nodes = (const int*)  d_in[3];
    const int*   adj_edges = (const int*)  d_in[4];
    const float* W_self    = (const float*)d_in[5];
    const float* W_neigh   = (const float*)d_in[6];
    const float* W_edge    = (const float*)d_in[7];
    const float* attn      = (const float*)d_in[8];
    const float* fc_w      = (const float*)d_in[9];
    const float* fc_b      = (const float*)d_in[10];
    float* out = (float*)d_out;

    const int SMEM_G0 = 4 * 2 * H16SLAB * 2;   // 49152 (NS=4, fp16 slabs)
    static cudaStream_t s1 = nullptr;
    static cudaEvent_t  evA = nullptr, evB = nullptr;
    if (!s1) {
        cudaFuncSetAttribute(gemm_h0, cudaFuncAttributeMaxDynamicSharedMemorySize, SMEM_G0);
        cudaStreamCreateWithFlags(&s1, cudaStreamNonBlocking);
        cudaEventCreateWithFlags(&evA, cudaEventDisableTiming);
        cudaEventCreateWithFlags(&evB, cudaEventDisableTiming);
    }

    // default-stream prefix: fp16 table conversion, then weight pack + idx
    k_cvt<<<(NMP*NEDGE*E/4 + 255) / 256, 256>>>(feats, edge_emb);
    k_prep0<<<(NMP*2*288*128 + 255) / 256, 256>>>(ids, adj_nodes, adj_edges,
                                                  W_self, W_neigh, W_edge);
    cudaEventRecord(evA, 0);

    // side chain (under hop2): hop1 mean, ee pack, h0 GEMM
    cudaStreamWaitEvent(s1, evA, 0);
    k_mean_hop1<<<NMP * BB / 8, 256, 0, s1>>>();
    k_pack_e<<<NMP * M1 / 8, 256, 0, s1>>>();
    gemm_h_small<1><<<dim3(BB / 128, NMP), 256, 0, s1>>>(feats, ids, W_self, W_neigh, 0);
    cudaEventRecord(evB, s1);

    // main chain
    k_mean_hop2<<<NMP * M1 / 8, 256>>>(adj_nodes, adj_edges);
    gemm_h0<<<dim3(128, NMP), 256, SMEM_G0>>>();
    cudaStreamWaitEvent(0, evB, 0);
    gemm_edge<<<dim3(128, NMP), 256>>>();
    gemm_h_small<2><<<dim3(BB / 128, NMP), 256>>>(feats, ids, W_self, W_neigh, 1);
    k_fuse<<<BB / 8, 256>>>(attn, fc_w, fc_b, out);
}

// round 15
// speedup vs baseline: 1.1545x; 1.1545x over previous
#include <cuda_runtime.h>
#include <cuda_fp16.h>
#include <cstdint>

#define NMP     3
#define NNODES  50000
#define D       128
#define E       32
#define DEG     32
#define NEDGE   200000
#define BB      1024
#define S       16
#define NC      8
#define M1      (BB*S)      /* 16384 */
#define DE      (D+E)       /* 160 */

#define NSTG    18          /* 288 / 16 k-stages */
#define ASLAB   2560        /* fp32 slab for edge pack: 128 rows * 20 floats */
#define KPA     24          /* fp16 A smem stride (halves), 48B rows */
#define H16SLAB (128*KPA)   /* 3072 halves = 6144B per k16 stage */
#define EBSLAB  640         /* 16 k * 40 floats (32 data + 8 pad)   */

// ---------------- scratch (static device globals; no runtime alloc) ----------------
__device__ int    g_nb1 [NMP*M1];
__device__ int    g_eid1[NMP*M1];
__device__ float  g_nin1[NMP*BB*DE];
__device__ float  g_h0  [NMP*BB*D];
__device__ float  g_ninL1[NMP*BB*DE];
__device__ float  g_outs[NMP*BB*D];
__device__ __half g_a1pk16[(size_t)NMP*128*NSTG*H16SLAB];   // fp16 packed A
__device__ float  g_epk[(size_t)NMP*128*10*ASLAB];
__device__ __half g_Whpk16[NMP*2*NSTG*H16SLAB];             // fp16 packed Wh, n-major
__device__ float  g_Wepk[NMP*2*NSTG*EBSLAB];

// ---------------- helpers ----------------
__device__ __forceinline__ float tf32r(float x) {
    uint32_t u; asm("cvt.rna.tf32.f32 %0, %1;" : "=r"(u) : "f"(x));
    return __uint_as_float(u);
}
__device__ __forceinline__ uint32_t fu(float x) { return __float_as_uint(x); }
__device__ __forceinline__ uint32_t sptr(const void* p) {
    return (uint32_t)__cvta_generic_to_shared(p);
}
__device__ __forceinline__ void ldsm_x4(uint32_t& d0, uint32_t& d1, uint32_t& d2, uint32_t& d3,
                                        uint32_t a) {
    asm volatile("ldmatrix.sync.aligned.m8n8.x4.shared.b16 {%0,%1,%2,%3}, [%4];"
        : "=r"(d0), "=r"(d1), "=r"(d2), "=r"(d3) : "r"(a));
}
__device__ __forceinline__ uint32_t cvt_frag(uint32_t v) {
    return fu(tf32r(__uint_as_float(v)));
}
__device__ __forceinline__ float wred(float v) {
    #pragma unroll
    for (int o = 16; o; o >>= 1) v += __shfl_xor_sync(0xffffffffu, v, o);
    return v;
}
__device__ __forceinline__ uint32_t h2pack(float a, float b) {
    __half2 h = __floats2half2_rn(a, b);
    return *(uint32_t*)&h;
}

#define MMA_TF32(c, a, b) \
    asm volatile("mma.sync.aligned.m16n8k8.row.col.f32.tf32.tf32.f32 " \
        "{%0,%1,%2,%3}, {%4,%5,%6,%7}, {%8,%9}, {%0,%1,%2,%3};" \
        : "+f"((c)[0]), "+f"((c)[1]), "+f"((c)[2]), "+f"((c)[3]) \
        : "r"((a)[0]), "r"((a)[1]), "r"((a)[2]), "r"((a)[3]), \
          "r"((b)[0]), "r"((b)[1]))

#define MMA_F16(c, a, b) \
    asm volatile("mma.sync.aligned.m16n8k16.row.col.f32.f16.f16.f32 " \
        "{%0,%1,%2,%3}, {%4,%5,%6,%7}, {%8,%9}, {%0,%1,%2,%3};" \
        : "+f"((c)[0]), "+f"((c)[1]), "+f"((c)[2]), "+f"((c)[3]) \
        : "r"((a)[0]), "r"((a)[1]), "r"((a)[2]), "r"((a)[3]), \
          "r"((b)[0]), "r"((b)[1]))

#define MBAR_INIT(addr, cnt) \
    asm volatile("mbarrier.init.shared.b64 [%0], %1;" :: "r"(addr), "r"(cnt) : "memory")
#define MBAR_EXPECT_TX(addr, bytes) \
    asm volatile("mbarrier.arrive.expect_tx.shared.b64 _, [%0], %1;" :: "r"(addr), "r"(bytes) : "memory")
#define MBAR_ARRIVE(addr) \
    asm volatile("mbarrier.arrive.shared.b64 _, [%0];" :: "r"(addr) : "memory")
#define MBAR_WAIT(addr, parity) do {                                            \
    uint32_t _m = (addr); uint32_t _p = (parity); uint32_t _done;               \
    asm volatile("{\n\t.reg .pred p;\n\t"                                       \
        "mbarrier.try_wait.parity.acquire.cta.shared::cta.b64 p, [%1], %2;\n\t" \
        "selp.b32 %0, 1, 0, p;\n\t}"                                            \
        : "=r"(_done) : "r"(_m), "r"(_p) : "memory");                           \
    if (!_done) {                                                               \
        asm volatile("{\n\t.reg .pred P1;\n\t"                                  \
            "WL_%=:\n\t"                                                        \
            "mbarrier.try_wait.parity.acquire.cta.shared::cta.b64 P1, [%0], %1, 0x989680;\n\t" \
            "@P1 bra.uni WD_%=;\n\t"                                            \
            "bra.uni WL_%=;\n\t"                                                \
            "WD_%=:\n\t}"                                                       \
            :: "r"(_m), "r"(_p) : "memory");                                    \
    }                                                                           \
} while (0)
#define BULK_CP(dst, src, bytes, mbar) \
    asm volatile("cp.async.bulk.shared::cta.global.mbarrier::complete_tx::bytes [%0], [%1], %2, [%3];" \
        :: "r"(dst), "l"(src), "r"(bytes), "r"(mbar) : "memory")

#define CP16(d, s)  asm volatile("cp.async.cg.shared.global [%0], [%1], 16;" :: "r"(d), "l"(s))
#define CP_COMMIT   asm volatile("cp.async.commit_group;" ::)
#define CP_WAIT(n)  asm volatile("cp.async.wait_group %0;" :: "n"(n))

// ---------------- 0) merged prefix: fp16 weight pack + edge weight pack + hop-1 ids ----------------
__global__ void k_prep0(const int* __restrict__ ids,
                        const int* __restrict__ adj_nodes,
                        const int* __restrict__ adj_edges,
                        const float* __restrict__ W_self,
                        const float* __restrict__ W_neigh,
                        const float* __restrict__ W_edge) {
    int t = blockIdx.x * blockDim.x + threadIdx.x;
    if (t < NMP*2*288*128) {
        int wl = t / (288*128);
        int r  = t % (288*128);
        int k  = r / 128, n = r % 128;
        float v = (k < 128) ? W_self [wl*128*128 + k*128 + n]
                            : W_neigh[wl*160*128 + (k-128)*128 + n];
        g_Whpk16[(size_t)(wl*NSTG + (k>>4))*H16SLAB + n*KPA + (k&15)] = __float2half(v);
    }
    if (t < NMP*2*288*32) {
        int wl = t / (288*32);
        int r  = t % (288*32);
        int k  = r / 32, n = r % 32;
        g_Wepk[(size_t)(wl*NSTG + (k>>4))*EBSLAB + (k&15)*40 + n] = tf32r(W_edge[t]);
    }
    if (t < NMP * M1) {
        int mp = t / M1;
        int r  = t % M1;
        int b  = r >> 4;
        int s  = r & 15;
        long base = ((long)mp * NNODES + ids[b]) * DEG + s;
        g_nb1[t]  = adj_nodes[base];
        g_eid1[t] = adj_edges[base];
    }
}

// ---------------- 2) hop-2 gather + mean + fp16 A-pack ----------------
__global__ void k_mean_hop2(const float* __restrict__ feats,
                            const float* __restrict__ edge_emb,
                            const int* __restrict__ adj_nodes,
                            const int* __restrict__ adj_edges) {
    int w    = (blockIdx.x * blockDim.x + threadIdx.x) >> 5;
    int lane = threadIdx.x & 31;
    if (w >= NMP * M1) return;
    int mp = w / M1;
    int m  = w % M1;
    int nb1 = g_nb1[w];
    long abase = ((long)mp * NNODES + nb1) * DEG;
    const int* an = adj_nodes + abase;
    const int* ae = adj_edges + abase;
    float4 aF = make_float4(0.f,0.f,0.f,0.f);
    float4 aE = make_float4(0.f,0.f,0.f,0.f);
    #pragma unroll
    for (int s = 0; s < S; s++) {
        int nb = an[s];
        float4 v = ((const float4*)(feats + (long)nb * D))[lane];
        aF.x += v.x; aF.y += v.y; aF.z += v.z; aF.w += v.w;
        if (lane < E/4) {
            int e = ae[s];
            float4 u = ((const float4*)(edge_emb + ((long)mp * NEDGE + e) * E))[lane];
            aE.x += u.x; aE.y += u.y; aE.z += u.z; aE.w += u.w;
        }
    }
    const float inv = 1.0f / S;
    int blk = m >> 7, r = m & 127;
    size_t pb = (size_t)(mp * 128 + blk) * NSTG;
    int sq = lane >> 2, o = (lane & 3) * 4;
    float4 fv = ((const float4*)(feats + (size_t)nb1 * D))[lane];
    {
        uint2 pk; pk.x = h2pack(fv.x, fv.y); pk.y = h2pack(fv.z, fv.w);
        *(uint2*)&g_a1pk16[(pb + sq) * H16SLAB + r * KPA + o] = pk;
    }
    {
        uint2 pk; pk.x = h2pack(aF.x*inv, aF.y*inv); pk.y = h2pack(aF.z*inv, aF.w*inv);
        *(uint2*)&g_a1pk16[(pb + 8 + sq) * H16SLAB + r * KPA + o] = pk;
    }
    if (lane < E/4) {
        uint2 pk; pk.x = h2pack(aE.x*inv, aE.y*inv); pk.y = h2pack(aE.z*inv, aE.w*inv);
        *(uint2*)&g_a1pk16[(pb + 16 + sq) * H16SLAB + r * KPA + o] = pk;
    }
}

// ---------------- 3) hop-1 gather + mean -> nin1 ----------------
__global__ void k_mean_hop1(const float* __restrict__ feats,
                            const float* __restrict__ edge_emb) {
    int w    = (blockIdx.x * blockDim.x + threadIdx.x) >> 5;
    int lane = threadIdx.x & 31;
    if (w >= NMP * BB) return;
    int mp = w / BB;
    int b  = w % BB;
    int base = mp * M1 + b * S;
    float4 aF = make_float4(0.f,0.f,0.f,0.f);
    float4 aE = make_float4(0.f,0.f,0.f,0.f);
    #pragma unroll
    for (int s = 0; s < S; s++) {
        int nb = g_nb1[base + s];
        float4 v = ((const float4*)(feats + (long)nb * D))[lane];
        aF.x += v.x; aF.y += v.y; aF.z += v.z; aF.w += v.w;
        if (lane < E/4) {
            int e = g_eid1[base + s];
            float4 u = ((const float4*)(edge_emb + ((long)mp * NEDGE + e) * E))[lane];
            aE.x += u.x; aE.y += u.y; aE.z += u.z; aE.w += u.w;
        }
    }
    const float inv = 1.0f / S;
    float4* o = (float4*)(g_nin1 + (size_t)w * DE);
    o[lane] = make_float4(aF.x*inv, aF.y*inv, aF.z*inv, aF.w*inv);
    if (lane < E/4)
        o[D/4 + lane] = make_float4(aE.x*inv, aE.y*inv, aE.z*inv, aE.w*inv);
}

// ---------------- 3b) pack ee1 gather -> g_epk slabs 8..9 ----------------
__global__ void k_pack_e(const float* __restrict__ edge_emb) {
    int w    = (blockIdx.x * blockDim.x + threadIdx.x) >> 5;
    int lane = threadIdx.x & 31;
    if (w >= NMP * M1) return;
    int mp = w / M1;
    int m  = w % M1;
    int e  = g_eid1[w];
    float v = edge_emb[((size_t)mp * NEDGE + e) * E + lane];
    int blk = m >> 7, r = m & 127;
    g_epk[((size_t)(mp*128 + blk)*10 + 8 + (lane >> 4)) * ASLAB + r*20 + (lane & 15)] = v;
}

// ---------------- gemm_h0: fp16 HMMA (m16n8k16) + bulk-DMA, NS=4 ----------------
__global__ __launch_bounds__(256) void gemm_h0() {
    constexpr int NS = 4;
    constexpr uint32_t STG_BYTES = 2 * H16SLAB * 2;
    extern __shared__ __half hsm[];
    __shared__ __align__(8) uint64_t mbar[2 * NS];

    int mp  = blockIdx.y;
    int blk = blockIdx.x;
    int m0  = blk * 128;
    int tid  = threadIdx.x;
    int lane = tid & 31;
    int w    = tid >> 5;
    int wm   = w >> 2;
    int wn   = w & 3;
    uint32_t lmoff = (uint32_t)((lane & 15) * KPA * 2 + (lane >> 4) * 16);

    uint32_t full0  = sptr(&mbar[0]);
    uint32_t empty0 = sptr(&mbar[NS]);

    if (tid == 0) {
        #pragma unroll
        for (int s = 0; s < NS; s++) {
            MBAR_INIT(full0  + s * 8, 1);
            MBAR_INIT(empty0 + s * 8, 256);
        }
    }
    __syncthreads();

    const __half* Asrc = g_a1pk16 + (size_t)(mp * 128 + blk) * NSTG * H16SLAB;
    const __half* Bsrc = g_Whpk16 + (size_t)(mp * 2 + 0) * NSTG * H16SLAB;
    uint32_t smem0 = sptr(hsm);

    if (tid == 0) {
        #pragma unroll
        for (int t = 0; t < NS - 1; t++) {
            uint32_t fb = full0 + t * 8;
            uint32_t sa = smem0 + t * STG_BYTES;
            MBAR_EXPECT_TX(fb, STG_BYTES);
            BULK_CP(sa,               Asrc + (size_t)t * H16SLAB, H16SLAB * 2, fb);
            BULK_CP(sa + H16SLAB * 2, Bsrc + (size_t)t * H16SLAB, H16SLAB * 2, fb);
        }
    }

    float acc[4][4][4];
    #pragma unroll
    for (int i = 0; i < 4; i++)
        #pragma unroll
        for (int j = 0; j < 4; j++)
            #pragma unroll
            for (int q = 0; q < 4; q++) acc[i][j][q] = 0.f;

    int cslot = 0, cph = 0;
    int pslot = NS - 1, pph = 1;

    for (int s = 0; s < NSTG; s++) {
        if (tid == 0) {
            int t = s + NS - 1;
            if (t < NSTG) {
                MBAR_WAIT(empty0 + pslot * 8, pph);
                uint32_t fb = full0 + pslot * 8;
                uint32_t sa = smem0 + pslot * STG_BYTES;
                MBAR_EXPECT_TX(fb, STG_BYTES);
                BULK_CP(sa,               Asrc + (size_t)t * H16SLAB, H16SLAB * 2, fb);
                BULK_CP(sa + H16SLAB * 2, Bsrc + (size_t)t * H16SLAB, H16SLAB * 2, fb);
                if (++pslot == NS) { pslot = 0; pph ^= 1; }
            }
        }
        MBAR_WAIT(full0 + cslot * 8, cph);

        __half* As = hsm + cslot * 2 * H16SLAB;
        __half* Bs = As + H16SLAB;
        uint32_t as_base = sptr(As);
        uint32_t afr[4][4], bfr[4][2];
        #pragma unroll
        for (int mt = 0; mt < 4; mt++) {
            uint32_t ad = as_base + (uint32_t)((wm * 64 + mt * 16) * KPA * 2) + lmoff;
            ldsm_x4(afr[mt][0], afr[mt][1], afr[mt][2], afr[mt][3], ad);
        }
        #pragma unroll
        for (int nt = 0; nt < 4; nt++) {
            int n = wn * 32 + nt * 8 + (lane >> 2);
            const uint32_t* bp = (const uint32_t*)(Bs + n * KPA);
            bfr[nt][0] = bp[lane & 3];
            bfr[nt][1] = bp[4 + (lane & 3)];
        }
        #pragma unroll
        for (int mt = 0; mt < 4; mt++)
            #pragma unroll
            for (int nt = 0; nt < 4; nt++)
                MMA_F16(acc[mt][nt], afr[mt], bfr[nt]);

        MBAR_ARRIVE(empty0 + cslot * 8);
        if (++cslot == NS) { cslot = 0; cph ^= 1; }
    }

    #pragma unroll
    for (int mt = 0; mt < 4; mt++)
        #pragma unroll
        for (int nt = 0; nt < 4; nt++)
            #pragma unroll
            for (int q = 0; q < 4; q++)
                acc[mt][nt][q] = fmaxf(acc[mt][nt][q], 0.f);

    float* epb = g_epk + (size_t)(mp * 128 + blk) * 10 * ASLAB;
    int q8 = lane >> 2, c4 = lane & 3;
    #pragma unroll
    for (int mt = 0; mt < 4; mt++) {
        int r = wm * 64 + mt * 16 + q8;
        #pragma unroll
        for (int nt = 0; nt < 4; nt++) {
            int slab = wn * 2 + (nt >> 1);
            int ci   = (nt & 1) * 8 + 2 * c4;
            *(float2*)&epb[(size_t)slab * ASLAB + r       * 20 + ci] = make_float2(acc[mt][nt][0], acc[mt][nt][1]);
            *(float2*)&epb[(size_t)slab * ASLAB + (r + 8) * 20 + ci] = make_float2(acc[mt][nt][2], acc[mt][nt][3]);
        }
    }

    const float inv16 = 1.0f / 16.0f;
    #pragma unroll
    for (int mt = 0; mt < 4; mt++) {
        int b = (m0 + wm * 64 + mt * 16) >> 4;
        float* dst = g_ninL1 + ((size_t)mp * BB + b) * DE;
        #pragma unroll
        for (int nt = 0; nt < 4; nt++) {
            float s0 = acc[mt][nt][0] + acc[mt][nt][2];
            float s1 = acc[mt][nt][1] + acc[mt][nt][3];
            #pragma unroll
            for (int o = 4; o < 32; o <<= 1) {
                s0 += __shfl_xor_sync(0xffffffffu, s0, o);
                s1 += __shfl_xor_sync(0xffffffffu, s1, o);
            }
            if (lane < 4) {
                int c = wn * 32 + nt * 8 + 2 * lane;
                *(float2*)(dst + c) = make_float2(s0 * inv16, s1 * inv16);
            }
        }
    }
}

// ---------------- gemm_edge: bulk-DMA staged TF32; mean(relu(.)) -> ninL1[:, D:] ----------------
__global__ __launch_bounds__(256) void gemm_edge() {
    constexpr int NS   = 3;
    constexpr int SLOT = ASLAB + EBSLAB;
    __shared__ float ring[NS * SLOT];
    __shared__ float h0t[8 * 128];
    __shared__ __align__(8) uint64_t mbar[2 * NS + 1];

    int mp  = blockIdx.y;
    int blk = blockIdx.x;
    int m0  = blk * 128;
    int tid  = threadIdx.x;
    int lane = tid & 31;
    int w    = tid >> 5;
    int q    = lane >> 2;
    int c4   = lane & 3;
    int row16 = lane & 15;
    int sel4  = (lane >> 4) * 4;
    uint32_t lmoff = (uint32_t)((row16 * 20 + sel4) * 4);

    uint32_t full0  = sptr(&mbar[0]);
    uint32_t empty0 = sptr(&mbar[NS]);
    uint32_t h0bar  = sptr(&mbar[2 * NS]);

    if (tid == 0) {
        #pragma unroll
        for (int s = 0; s < NS; s++) {
            MBAR_INIT(full0  + s * 8, 1);
            MBAR_INIT(empty0 + s * 8, 256);
        }
        MBAR_INIT(h0bar, 1);
    }
    __syncthreads();

    const float* Apk = g_epk  + (size_t)(mp * 128 + blk) * 10 * ASLAB;
    const float* Bpk = g_Wepk + (size_t)(mp * 2 + 0) * NSTG * EBSLAB;
    const float* H0s = g_h0 + ((size_t)mp * BB + (m0 >> 4)) * D;
    uint32_t ring0 = sptr(ring);

#define ISSUE_EDGE(T, SLOTI) do {                                               \
    int _t = (T);                                                               \
    uint32_t fb = full0 + (SLOTI) * 8;                                          \
    uint32_t sa = ring0 + (SLOTI) * SLOT * 4;                                   \
    uint32_t bytes = EBSLAB * 4 + ((_t >= 8) ? ASLAB * 4 : 0);                  \
    MBAR_EXPECT_TX(fb, bytes);                                                  \
    if (_t >= 8)                                                                \
        BULK_CP(sa, Apk + (size_t)(_t - 8) * ASLAB, ASLAB * 4, fb);             \
    BULK_CP(sa + ASLAB * 4, Bpk + (size_t)_t * EBSLAB, EBSLAB * 4, fb);         \
} while (0)

    if (tid == 0) {
        MBAR_EXPECT_TX(h0bar, 8 * 128 * 4);
        BULK_CP(sptr(h0t), H0s, 8 * 128 * 4, h0bar);
        #pragma unroll
        for (int t = 0; t < NS - 1; t++) ISSUE_EDGE(t, t);
    }
    MBAR_WAIT(h0bar, 0);

    float acc[4][4];
    #pragma unroll
    for (int j = 0; j < 4; j++)
        #pragma unroll
        for (int t = 0; t < 4; t++) acc[j][t] = 0.f;

    int cslot = 0, cph = 0;
    int pslot = NS - 1, pph = 1;

    for (int s = 0; s < NSTG; s++) {
        if (tid == 0) {
            int t = s + NS - 1;
            if (t < NSTG) {
                MBAR_WAIT(empty0 + pslot * 8, pph);
                ISSUE_EDGE(t, pslot);
                if (++pslot == NS) { pslot = 0; pph ^= 1; }
            }
        }
        MBAR_WAIT(full0 + cslot * 8, cph);

        float* As = ring + cslot * SLOT;
        float* Bs = As + ASLAB;
        uint32_t as_base = sptr(As);
        #pragma unroll
        for (int kk = 0; kk < 16; kk += 8) {
            uint32_t afr[4], bfr[4][2];
            if (s < 8) {
                int kb = s * 16 + kk;
                uint32_t v0 = fu(tf32r(h0t[w * 128 + kb + c4]));
                uint32_t v1 = fu(tf32r(h0t[w * 128 + kb + c4 + 4]));
                afr[0] = v0; afr[1] = v0; afr[2] = v1; afr[3] = v1;
            } else {
                uint32_t ad = as_base + (uint32_t)(((w * 16) * 20 + kk) * 4) + lmoff;
                ldsm_x4(afr[0], afr[1], afr[2], afr[3], ad);
                afr[0] = cvt_frag(afr[0]);
                afr[1] = cvt_frag(afr[1]);
                afr[2] = cvt_frag(afr[2]);
                afr[3] = cvt_frag(afr[3]);
            }
            #pragma unroll
            for (int nt = 0; nt < 4; nt++) {
                int cN = nt * 8 + q;
                bfr[nt][0] = fu(Bs[(kk     + c4) * 40 + cN]);
                bfr[nt][1] = fu(Bs[(kk + 4 + c4) * 40 + cN]);
            }
            #pragma unroll
            for (int nt = 0; nt < 4; nt++)
                MMA_TF32(acc[nt], afr, bfr[nt]);
        }

        MBAR_ARRIVE(empty0 + cslot * 8);
        if (++cslot == NS) { cslot = 0; cph ^= 1; }
    }
#undef ISSUE_EDGE

    const float inv16 = 1.0f / 16.0f;
    int b = (m0 >> 4) + w;
    float* dst = g_ninL1 + ((size_t)mp * BB + b) * DE + D;
    #pragma unroll
    for (int nt = 0; nt < 4; nt++) {
        float s0 = fmaxf(acc[nt][0], 0.f) + fmaxf(acc[nt][2], 0.f);
        float s1 = fmaxf(acc[nt][1], 0.f) + fmaxf(acc[nt][3], 0.f);
        #pragma unroll
        for (int o = 4; o < 32; o <<= 1) {
            s0 += __shfl_xor_sync(0xffffffffu, s0, o);
            s1 += __shfl_xor_sync(0xffffffffu, s1, o);
        }
        if (lane < 4) {
            int c = nt * 8 + 2 * lane;
            *(float2*)(dst + c) = make_float2(s0 * inv16, s1 * inv16);
        }
    }
}

// ---------------- small node GEMM: cp.async 4-stage ring (latency-hidden), M=1024 ----------------
// MODE 1: h0 (l=0, P1=feats[ids], P2=nin1) -> g_h0
// MODE 2: outs (l=1, P1=g_h0, P2=ninL1)   -> g_outs
template<int MODE>
__global__ __launch_bounds__(256) void gemm_h_small(const float* __restrict__ feats,
                                                    const int*   __restrict__ ids,
                                                    const float* __restrict__ W_self,
                                                    const float* __restrict__ W_neigh,
                                                    int l) {
    constexpr int KTOT = D + DE;
    constexpr int NSG  = KTOT / 16;       // 18
    constexpr int NS   = 4;
    int mp = blockIdx.y;
    int m0 = blockIdx.x * 128;

    extern __shared__ float dsm[];
    float* Asd = dsm;                     // [NS][128][20]
    float* Bsd = dsm + NS * 128 * 20;     // [NS][16][136]
#define AS(b,r,k) Asd[((b)*128 + (r))*20 + (k)]
#define BS(b,k,n) Bsd[((b)*16  + (k))*136 + (n)]
    __shared__ const float* rowp[128];

    int tid  = threadIdx.x;
    int lane = tid & 31;
    int w    = tid >> 5;
    int wm   = w >> 2;
    int wn   = w & 3;
    int ar   = tid >> 1;
    int kq   = (tid & 1) * 8;
    int bk   = tid >> 4;
    int bn   = (tid & 15) * 8;
    int row16 = lane & 15;
    int sel4  = (lane >> 4) * 4;
    uint32_t lmoff = (uint32_t)((row16 * 20 + sel4) * 4);

    const float* P2 = (MODE == 1) ? g_nin1 : g_ninL1;
    float* Out      = (MODE == 1) ? g_h0   : g_outs;

    if (tid < 128) {
        int m = m0 + tid;
        rowp[tid] = (MODE == 1) ? (feats + (long)ids[m] * D)
                                : (g_h0 + ((long)mp * BB + m) * D);
    }
    __syncthreads();

    const float* Wsp = W_self  + ((long)(mp * 2 + l)) * D  * D;
    const float* Wnp = W_neigh + ((long)(mp * 2 + l)) * DE * D;
    const float* P2p = P2 + ((size_t)mp * BB + m0) * DE;

    float acc[4][4][4];
    #pragma unroll
    for (int i = 0; i < 4; i++)
        #pragma unroll
        for (int j = 0; j < 4; j++)
            #pragma unroll
            for (int q = 0; q < 4; q++) acc[i][j][q] = 0.f;

#define ISSUE_SM(SS) do {                                                       \
    int _s = (SS);                                                              \
    if (_s < NSG) {                                                             \
        int _k = _s * 16;                                                       \
        int _b = _s % NS;                                                       \
        const float* ap = (_k < D) ? rowp[ar] + _k                              \
                                   : P2p + (long)ar * DE + (_k - D);            \
        uint32_t da = sptr(&AS(_b, ar, kq));                                    \
        CP16(da,      ap + kq);                                                 \
        CP16(da + 16, ap + kq + 4);                                             \
        const float* wrow = (_k < D) ? (Wsp + (long)(_k + bk) * D)              \
                                     : (Wnp + (long)(_k - D + bk) * D);         \
        uint32_t db = sptr(&BS(_b, bk, bn));                                    \
        CP16(db,      wrow + bn);                                               \
        CP16(db + 16, wrow + bn + 4);                                           \
    }                                                                           \
    CP_COMMIT;                                                                  \
} while (0)

    ISSUE_SM(0); ISSUE_SM(1); ISSUE_SM(2);

    for (int it = 0; it < NSG; ++it) {
        CP_WAIT(NS - 2);
        __syncthreads();
        ISSUE_SM(it + NS - 1);

        int cur = it % NS;
        uint32_t as_base = sptr(&AS(cur, 0, 0));
        #pragma unroll
        for (int kk = 0; kk < 16; kk += 8) {
            uint32_t afr[4][4], bfr[4][2];
            #pragma unroll
            for (int mt = 0; mt < 4; mt++) {
                uint32_t ad = as_base + (uint32_t)(((wm * 64 + mt * 16) * 20 + kk) * 4) + lmoff;
                ldsm_x4(afr[mt][0], afr[mt][1], afr[mt][2], afr[mt][3], ad);
                afr[mt][0] = cvt_frag(afr[mt][0]);
                afr[mt][1] = cvt_frag(afr[mt][1]);
                afr[mt][2] = cvt_frag(afr[mt][2]);
                afr[mt][3] = cvt_frag(afr[mt][3]);
            }
            #pragma unroll
            for (int nt = 0; nt < 4; nt++) {
                int cN = wn * 32 + nt * 8 + (lane >> 2);
                bfr[nt][0] = cvt_frag(fu(BS(cur, kk     + (lane & 3), cN)));
                bfr[nt][1] = cvt_frag(fu(BS(cur, kk + 4 + (lane & 3), cN)));
            }
            #pragma unroll
            for (int mt = 0; mt < 4; mt++)
                #pragma unroll
                for (int nt = 0; nt < 4; nt++)
                    MMA_TF32(acc[mt][nt], afr[mt], bfr[nt]);
        }
        __syncthreads();
    }
#undef ISSUE_SM
#undef AS
#undef BS

    size_t ob = ((size_t)mp * BB + m0) * D;
    #pragma unroll
    for (int mt = 0; mt < 4; mt++) {
        int r = wm * 64 + mt * 16 + (lane >> 2);
        #pragma unroll
        for (int nt = 0; nt < 4; nt++) {
            int c = wn * 32 + nt * 8 + 2 * (lane & 3);
            float2 v0, v1;
            v0.x = fmaxf(acc[mt][nt][0], 0.f); v0.y = fmaxf(acc[mt][nt][1], 0.f);
            v1.x = fmaxf(acc[mt][nt][2], 0.f); v1.y = fmaxf(acc[mt][nt][3], 0.f);
            *(float2*)(Out + ob + (size_t)r       * D + c) = v0;
            *(float2*)(Out + ob + (size_t)(r + 8) * D + c) = v1;
        }
    }
}

// ---------------- final fuse: warp-per-row, shuffle-only reductions ----------------
__global__ __launch_bounds__(256) void k_fuse(const float* __restrict__ attn,
                                              const float* __restrict__ fc_w,
                                              const float* __restrict__ fc_b,
                                              float* __restrict__ out) {
    __shared__ float sfw[D * NC];
    int tid = threadIdx.x;
    for (int i = tid; i < D * NC; i += 256) sfw[i] = fc_w[i];
    __syncthreads();

    int warp = tid >> 5, lane = tid & 31;
    int b = blockIdx.x * 8 + warp;
    int d0 = lane * 4;

    float4 v0 = *(const float4*)&g_outs[((size_t)0 * BB + b) * D + d0];
    float4 v1 = *(const float4*)&g_outs[((size_t)1 * BB + b) * D + d0];
    float4 v2 = *(const float4*)&g_outs[((size_t)2 * BB + b) * D + d0];
    float4 a  = *(const float4*)&attn[d0];

    float s0 = wred(v0.x*a.x + v0.y*a.y + v0.z*a.z + v0.w*a.w);
    float s1 = wred(v1.x*a.x + v1.y*a.y + v1.z*a.z + v1.w*a.w);
    float s2 = wred(v2.x*a.x + v2.y*a.y + v2.z*a.z + v2.w*a.w);
    s0 = tanhf(s0); s1 = tanhf(s1); s2 = tanhf(s2);
    float mx = fmaxf(s0, fmaxf(s1, s2));
    float e0 = expf(s0 - mx), e1 = expf(s1 - mx), e2 = expf(s2 - mx);
    float inv = 1.f / (e0 + e1 + e2);

    float em[4];
    em[0] = (e0*v0.x + e1*v1.x + e2*v2.x) * inv;
    em[1] = (e0*v0.y + e1*v1.y + e2*v2.y) * inv;
    em[2] = (e0*v0.z + e1*v1.z + e2*v2.z) * inv;
    em[3] = (e0*v0.w + e1*v1.w + e2*v2.w) * inv;

    float n2 = wred(em[0]*em[0] + em[1]*em[1] + em[2]*em[2] + em[3]*em[3]);
    float rn = 1.f / fmaxf(sqrtf(n2), 1e-12f);
    em[0] *= rn; em[1] *= rn; em[2] *= rn; em[3] *= rn;

    #pragma unroll
    for (int nc = 0; nc < NC; nc++) {
        float p = em[0] * sfw[(d0+0)*NC + nc] + em[1] * sfw[(d0+1)*NC + nc]
                + em[2] * sfw[(d0+2)*NC + nc] + em[3] * sfw[(d0+3)*NC + nc];
        p = wred(p);
        if (lane == 0) out[b * NC + nc] = p + fc_b[nc];
    }
}

// ---------------- launch ----------------
extern "C" void kernel_launch(void* const* d_in, const int* in_sizes, int n_in,
                              void* d_out, int out_size) {
    (void)in_sizes; (void)n_in; (void)out_size;
    const int*   ids       = (const int*)  d_in[0];
    const float* feats     = (const float*)d_in[1];
    const float* edge_emb  = (const float*)d_in[2];
    const int*   adj_nodes = (const int*)  d_in[3];
    const int*   adj_edges = (const int*)  d_in[4];
    const float* W_self    = (const float*)d_in[5];
    const float* W_neigh   = (const float*)d_in[6];
    const float* W_edge    = (const float*)d_in[7];
    const float* attn      = (const float*)d_in[8];
    const float* fc_w      = (const float*)d_in[9];
    const float* fc_b      = (const float*)d_in[10];
    float* out = (float*)d_out;

    const int SMEM_G0 = 4 * 2 * H16SLAB * 2;             // 49152 (NS=4, fp16 slabs)
    const int SMEM_SM = 4 * (128 * 20 + 16 * 136) * 4;   // 75776 (small GEMM NS=4 ring)
    static cudaStream_t s1 = nullptr;
    static cudaEvent_t  evA = nullptr, evB = nullptr;
    if (!s1) {
        cudaFuncSetAttribute(gemm_h0, cudaFuncAttributeMaxDynamicSharedMemorySize, SMEM_G0);
        cudaFuncSetAttribute(gemm_h_small<1>, cudaFuncAttributeMaxDynamicSharedMemorySize, SMEM_SM);
        cudaFuncSetAttribute(gemm_h_small<2>, cudaFuncAttributeMaxDynamicSharedMemorySize, SMEM_SM);
        cudaStreamCreateWithFlags(&s1, cudaStreamNonBlocking);
        cudaEventCreateWithFlags(&evA, cudaEventDisableTiming);
        cudaEventCreateWithFlags(&evB, cudaEventDisableTiming);
    }

    // default-stream prefix: merged weight-round + idx
    k_prep0<<<(NMP*2*288*128 + 255) / 256, 256>>>(ids, adj_nodes, adj_edges,
                                                  W_self, W_neigh, W_edge);
    cudaEventRecord(evA, 0);

    // side chain (under hop2): hop1 mean, ee pack, h0 GEMM
    cudaStreamWaitEvent(s1, evA, 0);
    k_mean_hop1<<<NMP * BB / 8, 256, 0, s1>>>(feats, edge_emb);
    k_pack_e<<<NMP * M1 / 8, 256, 0, s1>>>(edge_emb);
    gemm_h_small<1><<<dim3(BB / 128, NMP), 256, SMEM_SM, s1>>>(feats, ids, W_self, W_neigh, 0);
    cudaEventRecord(evB, s1);

    // main chain
    k_mean_hop2<<<NMP * M1 / 8, 256>>>(feats, edge_emb, adj_nodes, adj_edges);
    gemm_h0<<<dim3(128, NMP), 256, SMEM_G0>>>();
    cudaStreamWaitEvent(0, evB, 0);
    gemm_edge<<<dim3(128, NMP), 256>>>();
    gemm_h_small<2><<<dim3(BB / 128, NMP), 256, SMEM_SM>>>(feats, ids, W_self, W_neigh, 1);
    k_fuse<<<BB / 8, 256>>>(attn, fc_w, fc_b, out);
}

// round 17
// speedup vs baseline: 1.2092x; 1.0473x over previous
#include <cuda_runtime.h>
#include <cuda_fp16.h>
#include <cstdint>

#define NMP     3
#define NNODES  50000
#define D       128
#define E       32
#define DEG     32
#define NEDGE   200000
#define BB      1024
#define S       16
#define NC      8
#define M1      (BB*S)      /* 16384 */
#define DE      (D+E)       /* 160 */

#define NSTG    18          /* 288 / 16 k-stages */
#define ASLAB   2560        /* fp32 slab for edge pack: 128 rows * 20 floats */
#define KPA     24          /* fp16 A smem stride (halves), 48B rows */
#define H16SLAB (128*KPA)   /* 3072 halves = 6144B per k16 stage */
#define EBSLAB  640         /* 16 k * 40 floats (32 data + 8 pad)   */

// ---------------- scratch (static device globals; no runtime alloc) ----------------
__device__ int    g_nb1 [NMP*M1];
__device__ int    g_eid1[NMP*M1];
__device__ float  g_nin1[NMP*BB*DE];
__device__ float  g_h0  [NMP*BB*D];
__device__ float  g_ninL1[NMP*BB*DE];
__device__ float  g_outs[NMP*BB*D];
__device__ __half g_a1pk16[(size_t)NMP*128*NSTG*H16SLAB];   // fp16 packed A
__device__ float  g_epk[(size_t)NMP*128*10*ASLAB];
__device__ __half g_Whpk16[NMP*2*NSTG*H16SLAB];             // fp16 packed Wh, n-major
__device__ float  g_Wepk[NMP*2*NSTG*EBSLAB];

// ---------------- helpers ----------------
__device__ __forceinline__ float tf32r(float x) {
    uint32_t u; asm("cvt.rna.tf32.f32 %0, %1;" : "=r"(u) : "f"(x));
    return __uint_as_float(u);
}
__device__ __forceinline__ uint32_t fu(float x) { return __float_as_uint(x); }
__device__ __forceinline__ uint32_t sptr(const void* p) {
    return (uint32_t)__cvta_generic_to_shared(p);
}
__device__ __forceinline__ void ldsm_x4(uint32_t& d0, uint32_t& d1, uint32_t& d2, uint32_t& d3,
                                        uint32_t a) {
    asm volatile("ldmatrix.sync.aligned.m8n8.x4.shared.b16 {%0,%1,%2,%3}, [%4];"
        : "=r"(d0), "=r"(d1), "=r"(d2), "=r"(d3) : "r"(a));
}
__device__ __forceinline__ uint32_t cvt_frag(uint32_t v) {
    return fu(tf32r(__uint_as_float(v)));
}
__device__ __forceinline__ float wred(float v) {
    #pragma unroll
    for (int o = 16; o; o >>= 1) v += __shfl_xor_sync(0xffffffffu, v, o);
    return v;
}
__device__ __forceinline__ uint32_t h2pack(float a, float b) {
    __half2 h = __floats2half2_rn(a, b);
    return *(uint32_t*)&h;
}

#define MMA_TF32(c, a, b) \
    asm volatile("mma.sync.aligned.m16n8k8.row.col.f32.tf32.tf32.f32 " \
        "{%0,%1,%2,%3}, {%4,%5,%6,%7}, {%8,%9}, {%0,%1,%2,%3};" \
        : "+f"((c)[0]), "+f"((c)[1]), "+f"((c)[2]), "+f"((c)[3]) \
        : "r"((a)[0]), "r"((a)[1]), "r"((a)[2]), "r"((a)[3]), \
          "r"((b)[0]), "r"((b)[1]))

#define MMA_F16(c, a, b) \
    asm volatile("mma.sync.aligned.m16n8k16.row.col.f32.f16.f16.f32 " \
        "{%0,%1,%2,%3}, {%4,%5,%6,%7}, {%8,%9}, {%0,%1,%2,%3};" \
        : "+f"((c)[0]), "+f"((c)[1]), "+f"((c)[2]), "+f"((c)[3]) \
        : "r"((a)[0]), "r"((a)[1]), "r"((a)[2]), "r"((a)[3]), \
          "r"((b)[0]), "r"((b)[1]))

#define MBAR_INIT(addr, cnt) \
    asm volatile("mbarrier.init.shared.b64 [%0], %1;" :: "r"(addr), "r"(cnt) : "memory")
#define MBAR_EXPECT_TX(addr, bytes) \
    asm volatile("mbarrier.arrive.expect_tx.shared.b64 _, [%0], %1;" :: "r"(addr), "r"(bytes) : "memory")
#define MBAR_ARRIVE(addr) \
    asm volatile("mbarrier.arrive.shared.b64 _, [%0];" :: "r"(addr) : "memory")
#define MBAR_WAIT(addr, parity) do {                                            \
    uint32_t _m = (addr); uint32_t _p = (parity); uint32_t _done;               \
    asm volatile("{\n\t.reg .pred p;\n\t"                                       \
        "mbarrier.try_wait.parity.acquire.cta.shared::cta.b64 p, [%1], %2;\n\t" \
        "selp.b32 %0, 1, 0, p;\n\t}"                                            \
        : "=r"(_done) : "r"(_m), "r"(_p) : "memory");                           \
    if (!_done) {                                                               \
        asm volatile("{\n\t.reg .pred P1;\n\t"                                  \
            "WL_%=:\n\t"                                                        \
            "mbarrier.try_wait.parity.acquire.cta.shared::cta.b64 P1, [%0], %1, 0x989680;\n\t" \
            "@P1 bra.uni WD_%=;\n\t"                                            \
            "bra.uni WL_%=;\n\t"                                                \
            "WD_%=:\n\t}"                                                       \
            :: "r"(_m), "r"(_p) : "memory");                                    \
    }                                                                           \
} while (0)
#define BULK_CP(dst, src, bytes, mbar) \
    asm volatile("cp.async.bulk.shared::cta.global.mbarrier::complete_tx::bytes [%0], [%1], %2, [%3];" \
        :: "r"(dst), "l"(src), "r"(bytes), "r"(mbar) : "memory")

#define CP16(d, s)  asm volatile("cp.async.cg.shared.global [%0], [%1], 16;" :: "r"(d), "l"(s))
#define CP_COMMIT   asm volatile("cp.async.commit_group;" ::)
#define CP_WAIT(n)  asm volatile("cp.async.wait_group %0;" :: "n"(n))

// ---------------- 0) merged prefix: fp16 weight pack + edge weight pack + hop-1 ids ----------------
__global__ void k_prep0(const int* __restrict__ ids,
                        const int* __restrict__ adj_nodes,
                        const int* __restrict__ adj_edges,
                        const float* __restrict__ W_self,
                        const float* __restrict__ W_neigh,
                        const float* __restrict__ W_edge) {
    int t = blockIdx.x * blockDim.x + threadIdx.x;
    if (t < NMP*2*288*128) {
        int wl = t / (288*128);
        int r  = t % (288*128);
        int k  = r / 128, n = r % 128;
        float v = (k < 128) ? W_self [wl*128*128 + k*128 + n]
                            : W_neigh[wl*160*128 + (k-128)*128 + n];
        g_Whpk16[(size_t)(wl*NSTG + (k>>4))*H16SLAB + n*KPA + (k&15)] = __float2half(v);
    }
    if (t < NMP*2*288*32) {
        int wl = t / (288*32);
        int r  = t % (288*32);
        int k  = r / 32, n = r % 32;
        g_Wepk[(size_t)(wl*NSTG + (k>>4))*EBSLAB + (k&15)*40 + n] = tf32r(W_edge[t]);
    }
    if (t < NMP * M1) {
        int mp = t / M1;
        int r  = t % M1;
        int b  = r >> 4;
        int s  = r & 15;
        long base = ((long)mp * NNODES + ids[b]) * DEG + s;
        g_nb1[t]  = adj_nodes[base];
        g_eid1[t] = adj_edges[base];
    }
}

// ---------------- 2) hop-2 gather + mean + fp16 A-pack ----------------
__global__ void k_mean_hop2(const float* __restrict__ feats,
                            const float* __restrict__ edge_emb,
                            const int* __restrict__ adj_nodes,
                            const int* __restrict__ adj_edges) {
    int w    = (blockIdx.x * blockDim.x + threadIdx.x) >> 5;
    int lane = threadIdx.x & 31;
    if (w >= NMP * M1) return;
    int mp = w / M1;
    int m  = w % M1;
    int nb1 = g_nb1[w];
    long abase = ((long)mp * NNODES + nb1) * DEG;
    const int* an = adj_nodes + abase;
    const int* ae = adj_edges + abase;
    float4 aF = make_float4(0.f,0.f,0.f,0.f);
    float4 aE = make_float4(0.f,0.f,0.f,0.f);
    #pragma unroll
    for (int s = 0; s < S; s++) {
        int nb = an[s];
        float4 v = ((const float4*)(feats + (long)nb * D))[lane];
        aF.x += v.x; aF.y += v.y; aF.z += v.z; aF.w += v.w;
        if (lane < E/4) {
            int e = ae[s];
            float4 u = ((const float4*)(edge_emb + ((long)mp * NEDGE + e) * E))[lane];
            aE.x += u.x; aE.y += u.y; aE.z += u.z; aE.w += u.w;
        }
    }
    const float inv = 1.0f / S;
    int blk = m >> 7, r = m & 127;
    size_t pb = (size_t)(mp * 128 + blk) * NSTG;
    int sq = lane >> 2, o = (lane & 3) * 4;
    float4 fv = ((const float4*)(feats + (size_t)nb1 * D))[lane];
    {
        uint2 pk; pk.x = h2pack(fv.x, fv.y); pk.y = h2pack(fv.z, fv.w);
        *(uint2*)&g_a1pk16[(pb + sq) * H16SLAB + r * KPA + o] = pk;
    }
    {
        uint2 pk; pk.x = h2pack(aF.x*inv, aF.y*inv); pk.y = h2pack(aF.z*inv, aF.w*inv);
        *(uint2*)&g_a1pk16[(pb + 8 + sq) * H16SLAB + r * KPA + o] = pk;
    }
    if (lane < E/4) {
        uint2 pk; pk.x = h2pack(aE.x*inv, aE.y*inv); pk.y = h2pack(aE.z*inv, aE.w*inv);
        *(uint2*)&g_a1pk16[(pb + 16 + sq) * H16SLAB + r * KPA + o] = pk;
    }
}

// ---------------- 3) hop-1 gather + mean -> nin1 ----------------
__global__ void k_mean_hop1(const float* __restrict__ feats,
                            const float* __restrict__ edge_emb) {
    int w    = (blockIdx.x * blockDim.x + threadIdx.x) >> 5;
    int lane = threadIdx.x & 31;
    if (w >= NMP * BB) return;
    int mp = w / BB;
    int b  = w % BB;
    int base = mp * M1 + b * S;
    float4 aF = make_float4(0.f,0.f,0.f,0.f);
    float4 aE = make_float4(0.f,0.f,0.f,0.f);
    #pragma unroll
    for (int s = 0; s < S; s++) {
        int nb = g_nb1[base + s];
        float4 v = ((const float4*)(feats + (long)nb * D))[lane];
        aF.x += v.x; aF.y += v.y; aF.z += v.z; aF.w += v.w;
        if (lane < E/4) {
            int e = g_eid1[base + s];
            float4 u = ((const float4*)(edge_emb + ((long)mp * NEDGE + e) * E))[lane];
            aE.x += u.x; aE.y += u.y; aE.z += u.z; aE.w += u.w;
        }
    }
    const float inv = 1.0f / S;
    float4* o = (float4*)(g_nin1 + (size_t)w * DE);
    o[lane] = make_float4(aF.x*inv, aF.y*inv, aF.z*inv, aF.w*inv);
    if (lane < E/4)
        o[D/4 + lane] = make_float4(aE.x*inv, aE.y*inv, aE.z*inv, aE.w*inv);
}

// ---------------- 3b) pack ee1 gather -> g_epk slabs 8..9 ----------------
__global__ void k_pack_e(const float* __restrict__ edge_emb) {
    int w    = (blockIdx.x * blockDim.x + threadIdx.x) >> 5;
    int lane = threadIdx.x & 31;
    if (w >= NMP * M1) return;
    int mp = w / M1;
    int m  = w % M1;
    int e  = g_eid1[w];
    float v = edge_emb[((size_t)mp * NEDGE + e) * E + lane];
    int blk = m >> 7, r = m & 127;
    g_epk[((size_t)(mp*128 + blk)*10 + 8 + (lane >> 4)) * ASLAB + r*20 + (lane & 15)] = v;
}

// ---------------- gemm_h0: fp16 HMMA (m16n8k16) + bulk-DMA, NS=4 ----------------
__global__ __launch_bounds__(256) void gemm_h0() {
    constexpr int NS = 4;
    constexpr uint32_t STG_BYTES = 2 * H16SLAB * 2;
    extern __shared__ __half hsm[];
    __shared__ __align__(8) uint64_t mbar[2 * NS];

    int mp  = blockIdx.y;
    int blk = blockIdx.x;
    int m0  = blk * 128;
    int tid  = threadIdx.x;
    int lane = tid & 31;
    int w    = tid >> 5;
    int wm   = w >> 2;
    int wn   = w & 3;
    uint32_t lmoff = (uint32_t)((lane & 15) * KPA * 2 + (lane >> 4) * 16);

    uint32_t full0  = sptr(&mbar[0]);
    uint32_t empty0 = sptr(&mbar[NS]);

    if (tid == 0) {
        #pragma unroll
        for (int s = 0; s < NS; s++) {
            MBAR_INIT(full0  + s * 8, 1);
            MBAR_INIT(empty0 + s * 8, 256);
        }
    }
    __syncthreads();

    const __half* Asrc = g_a1pk16 + (size_t)(mp * 128 + blk) * NSTG * H16SLAB;
    const __half* Bsrc = g_Whpk16 + (size_t)(mp * 2 + 0) * NSTG * H16SLAB;
    uint32_t smem0 = sptr(hsm);

    if (tid == 0) {
        #pragma unroll
        for (int t = 0; t < NS - 1; t++) {
            uint32_t fb = full0 + t * 8;
            uint32_t sa = smem0 + t * STG_BYTES;
            MBAR_EXPECT_TX(fb, STG_BYTES);
            BULK_CP(sa,               Asrc + (size_t)t * H16SLAB, H16SLAB * 2, fb);
            BULK_CP(sa + H16SLAB * 2, Bsrc + (size_t)t * H16SLAB, H16SLAB * 2, fb);
        }
    }

    float acc[4][4][4];
    #pragma unroll
    for (int i = 0; i < 4; i++)
        #pragma unroll
        for (int j = 0; j < 4; j++)
            #pragma unroll
            for (int q = 0; q < 4; q++) acc[i][j][q] = 0.f;

    int cslot = 0, cph = 0;
    int pslot = NS - 1, pph = 1;

    for (int s = 0; s < NSTG; s++) {
        if (tid == 0) {
            int t = s + NS - 1;
            if (t < NSTG) {
                MBAR_WAIT(empty0 + pslot * 8, pph);
                uint32_t fb = full0 + pslot * 8;
                uint32_t sa = smem0 + pslot * STG_BYTES;
                MBAR_EXPECT_TX(fb, STG_BYTES);
                BULK_CP(sa,               Asrc + (size_t)t * H16SLAB, H16SLAB * 2, fb);
                BULK_CP(sa + H16SLAB * 2, Bsrc + (size_t)t * H16SLAB, H16SLAB * 2, fb);
                if (++pslot == NS) { pslot = 0; pph ^= 1; }
            }
        }
        MBAR_WAIT(full0 + cslot * 8, cph);

        __half* As = hsm + cslot * 2 * H16SLAB;
        __half* Bs = As + H16SLAB;
        uint32_t as_base = sptr(As);
        uint32_t afr[4][4], bfr[4][2];
        #pragma unroll
        for (int mt = 0; mt < 4; mt++) {
            uint32_t ad = as_base + (uint32_t)((wm * 64 + mt * 16) * KPA * 2) + lmoff;
            ldsm_x4(afr[mt][0], afr[mt][1], afr[mt][2], afr[mt][3], ad);
        }
        #pragma unroll
        for (int nt = 0; nt < 4; nt++) {
            int n = wn * 32 + nt * 8 + (lane >> 2);
            const uint32_t* bp = (const uint32_t*)(Bs + n * KPA);
            bfr[nt][0] = bp[lane & 3];
            bfr[nt][1] = bp[4 + (lane & 3)];
        }
        #pragma unroll
        for (int mt = 0; mt < 4; mt++)
            #pragma unroll
            for (int nt = 0; nt < 4; nt++)
                MMA_F16(acc[mt][nt], afr[mt], bfr[nt]);

        MBAR_ARRIVE(empty0 + cslot * 8);
        if (++cslot == NS) { cslot = 0; cph ^= 1; }
    }

    #pragma unroll
    for (int mt = 0; mt < 4; mt++)
        #pragma unroll
        for (int nt = 0; nt < 4; nt++)
            #pragma unroll
            for (int q = 0; q < 4; q++)
                acc[mt][nt][q] = fmaxf(acc[mt][nt][q], 0.f);

    float* epb = g_epk + (size_t)(mp * 128 + blk) * 10 * ASLAB;
    int q8 = lane >> 2, c4 = lane & 3;
    #pragma unroll
    for (int mt = 0; mt < 4; mt++) {
        int r = wm * 64 + mt * 16 + q8;
        #pragma unroll
        for (int nt = 0; nt < 4; nt++) {
            int slab = wn * 2 + (nt >> 1);
            int ci   = (nt & 1) * 8 + 2 * c4;
            *(float2*)&epb[(size_t)slab * ASLAB + r       * 20 + ci] = make_float2(acc[mt][nt][0], acc[mt][nt][1]);
            *(float2*)&epb[(size_t)slab * ASLAB + (r + 8) * 20 + ci] = make_float2(acc[mt][nt][2], acc[mt][nt][3]);
        }
    }

    const float inv16 = 1.0f / 16.0f;
    #pragma unroll
    for (int mt = 0; mt < 4; mt++) {
        int b = (m0 + wm * 64 + mt * 16) >> 4;
        float* dst = g_ninL1 + ((size_t)mp * BB + b) * DE;
        #pragma unroll
        for (int nt = 0; nt < 4; nt++) {
            float s0 = acc[mt][nt][0] + acc[mt][nt][2];
            float s1 = acc[mt][nt][1] + acc[mt][nt][3];
            #pragma unroll
            for (int o = 4; o < 32; o <<= 1) {
                s0 += __shfl_xor_sync(0xffffffffu, s0, o);
                s1 += __shfl_xor_sync(0xffffffffu, s1, o);
            }
            if (lane < 4) {
                int c = wn * 32 + nt * 8 + 2 * lane;
                *(float2*)(dst + c) = make_float2(s0 * inv16, s1 * inv16);
            }
        }
    }
}

// ---------------- gemm_edge: bulk-DMA staged TF32; mean(relu(.)) -> ninL1[:, D:] ----------------
__global__ __launch_bounds__(256) void gemm_edge() {
    constexpr int NS   = 3;
    constexpr int SLOT = ASLAB + EBSLAB;
    __shared__ float ring[NS * SLOT];
    __shared__ float h0t[8 * 128];
    __shared__ __align__(8) uint64_t mbar[2 * NS + 1];

    int mp  = blockIdx.y;
    int blk = blockIdx.x;
    int m0  = blk * 128;
    int tid  = threadIdx.x;
    int lane = tid & 31;
    int w    = tid >> 5;
    int q    = lane >> 2;
    int c4   = lane & 3;
    int row16 = lane & 15;
    int sel4  = (lane >> 4) * 4;
    uint32_t lmoff = (uint32_t)((row16 * 20 + sel4) * 4);

    uint32_t full0  = sptr(&mbar[0]);
    uint32_t empty0 = sptr(&mbar[NS]);
    uint32_t h0bar  = sptr(&mbar[2 * NS]);

    if (tid == 0) {
        #pragma unroll
        for (int s = 0; s < NS; s++) {
            MBAR_INIT(full0  + s * 8, 1);
            MBAR_INIT(empty0 + s * 8, 256);
        }
        MBAR_INIT(h0bar, 1);
    }
    __syncthreads();

    const float* Apk = g_epk  + (size_t)(mp * 128 + blk) * 10 * ASLAB;
    const float* Bpk = g_Wepk + (size_t)(mp * 2 + 0) * NSTG * EBSLAB;
    const float* H0s = g_h0 + ((size_t)mp * BB + (m0 >> 4)) * D;
    uint32_t ring0 = sptr(ring);

#define ISSUE_EDGE(T, SLOTI) do {                                               \
    int _t = (T);                                                               \
    uint32_t fb = full0 + (SLOTI) * 8;                                          \
    uint32_t sa = ring0 + (SLOTI) * SLOT * 4;                                   \
    uint32_t bytes = EBSLAB * 4 + ((_t >= 8) ? ASLAB * 4 : 0);                  \
    MBAR_EXPECT_TX(fb, bytes);                                                  \
    if (_t >= 8)                                                                \
        BULK_CP(sa, Apk + (size_t)(_t - 8) * ASLAB, ASLAB * 4, fb);             \
    BULK_CP(sa + ASLAB * 4, Bpk + (size_t)_t * EBSLAB, EBSLAB * 4, fb);         \
} while (0)

    if (tid == 0) {
        MBAR_EXPECT_TX(h0bar, 8 * 128 * 4);
        BULK_CP(sptr(h0t), H0s, 8 * 128 * 4, h0bar);
        #pragma unroll
        for (int t = 0; t < NS - 1; t++) ISSUE_EDGE(t, t);
    }
    MBAR_WAIT(h0bar, 0);

    float acc[4][4];
    #pragma unroll
    for (int j = 0; j < 4; j++)
        #pragma unroll
        for (int t = 0; t < 4; t++) acc[j][t] = 0.f;

    int cslot = 0, cph = 0;
    int pslot = NS - 1, pph = 1;

    for (int s = 0; s < NSTG; s++) {
        if (tid == 0) {
            int t = s + NS - 1;
            if (t < NSTG) {
                MBAR_WAIT(empty0 + pslot * 8, pph);
                ISSUE_EDGE(t, pslot);
                if (++pslot == NS) { pslot = 0; pph ^= 1; }
            }
        }
        MBAR_WAIT(full0 + cslot * 8, cph);

        float* As = ring + cslot * SLOT;
        float* Bs = As + ASLAB;
        uint32_t as_base = sptr(As);
        #pragma unroll
        for (int kk = 0; kk < 16; kk += 8) {
            uint32_t afr[4], bfr[4][2];
            if (s < 8) {
                int kb = s * 16 + kk;
                uint32_t v0 = fu(tf32r(h0t[w * 128 + kb + c4]));
                uint32_t v1 = fu(tf32r(h0t[w * 128 + kb + c4 + 4]));
                afr[0] = v0; afr[1] = v0; afr[2] = v1; afr[3] = v1;
            } else {
                uint32_t ad = as_base + (uint32_t)(((w * 16) * 20 + kk) * 4) + lmoff;
                ldsm_x4(afr[0], afr[1], afr[2], afr[3], ad);
                afr[0] = cvt_frag(afr[0]);
                afr[1] = cvt_frag(afr[1]);
                afr[2] = cvt_frag(afr[2]);
                afr[3] = cvt_frag(afr[3]);
            }
            #pragma unroll
            for (int nt = 0; nt < 4; nt++) {
                int cN = nt * 8 + q;
                bfr[nt][0] = fu(Bs[(kk     + c4) * 40 + cN]);
                bfr[nt][1] = fu(Bs[(kk + 4 + c4) * 40 + cN]);
            }
            #pragma unroll
            for (int nt = 0; nt < 4; nt++)
                MMA_TF32(acc[nt], afr, bfr[nt]);
        }

        MBAR_ARRIVE(empty0 + cslot * 8);
        if (++cslot == NS) { cslot = 0; cph ^= 1; }
    }
#undef ISSUE_EDGE

    const float inv16 = 1.0f / 16.0f;
    int b = (m0 >> 4) + w;
    float* dst = g_ninL1 + ((size_t)mp * BB + b) * DE + D;
    #pragma unroll
    for (int nt = 0; nt < 4; nt++) {
        float s0 = fmaxf(acc[nt][0], 0.f) + fmaxf(acc[nt][2], 0.f);
        float s1 = fmaxf(acc[nt][1], 0.f) + fmaxf(acc[nt][3], 0.f);
        #pragma unroll
        for (int o = 4; o < 32; o <<= 1) {
            s0 += __shfl_xor_sync(0xffffffffu, s0, o);
            s1 += __shfl_xor_sync(0xffffffffu, s1, o);
        }
        if (lane < 4) {
            int c = nt * 8 + 2 * lane;
            *(float2*)(dst + c) = make_float2(s0 * inv16, s1 * inv16);
        }
    }
}

// ---------------- small node GEMM MODE 1 (R13-proven LDG/STS path): side stream ----------------
__global__ __launch_bounds__(256) void gemm_h_small1(const float* __restrict__ feats,
                                                     const int*   __restrict__ ids,
                                                     const float* __restrict__ W_self,
                                                     const float* __restrict__ W_neigh) {
    constexpr int KTOT = D + DE;
    constexpr int NSG  = KTOT / 16;
    int mp = blockIdx.y;
    int m0 = blockIdx.x * 128;

    __shared__ float As[2][128][20];
    __shared__ float Bs[2][16][136];
    __shared__ const float* rowp[128];

    int tid  = threadIdx.x;
    int lane = tid & 31;
    int w    = tid >> 5;
    int wm   = w >> 2;
    int wn   = w & 3;
    int ar   = tid >> 1;
    int kq   = (tid & 1) * 8;
    int bk   = tid >> 4;
    int bn   = (tid & 15) * 8;
    int row16 = lane & 15;
    int sel4  = (lane >> 4) * 4;
    uint32_t lmoff = (uint32_t)((row16 * 20 + sel4) * 4);

    if (tid < 128) rowp[tid] = feats + (long)ids[m0 + tid] * D;
    __syncthreads();

    const float* Wsp = W_self  + ((long)(mp * 2)) * D  * D;
    const float* Wnp = W_neigh + ((long)(mp * 2)) * DE * D;
    const float* P2p = g_nin1 + ((size_t)mp * BB + m0) * DE;

    float acc[4][4][4];
    #pragma unroll
    for (int i = 0; i < 4; i++)
        #pragma unroll
        for (int j = 0; j < 4; j++)
            #pragma unroll
            for (int q = 0; q < 4; q++) acc[i][j][q] = 0.f;

    float4 ra0, ra1, rb0, rb1;
#define LDG_H(K0) do {                                                          \
    int _k = (K0);                                                              \
    const float* ap = (_k < D) ? rowp[ar] + _k                                  \
                               : P2p + (long)ar * DE + (_k - D);                \
    ra0 = *(const float4*)(ap + kq);                                            \
    ra1 = *(const float4*)(ap + kq + 4);                                        \
    const float* wrow = (_k < D) ? (Wsp + (long)(_k + bk) * D)                  \
                                 : (Wnp + (long)(_k - D + bk) * D);             \
    rb0 = *(const float4*)(wrow + bn);                                          \
    rb1 = *(const float4*)(wrow + bn + 4);                                      \
} while (0)
#define STS_H(BUF) do {                                                         \
    As[BUF][ar][kq+0] = tf32r(ra0.x); As[BUF][ar][kq+1] = tf32r(ra0.y);         \
    As[BUF][ar][kq+2] = tf32r(ra0.z); As[BUF][ar][kq+3] = tf32r(ra0.w);         \
    As[BUF][ar][kq+4] = tf32r(ra1.x); As[BUF][ar][kq+5] = tf32r(ra1.y);         \
    As[BUF][ar][kq+6] = tf32r(ra1.z); As[BUF][ar][kq+7] = tf32r(ra1.w);         \
    Bs[BUF][bk][bn+0] = tf32r(rb0.x); Bs[BUF][bk][bn+1] = tf32r(rb0.y);         \
    Bs[BUF][bk][bn+2] = tf32r(rb0.z); Bs[BUF][bk][bn+3] = tf32r(rb0.w);         \
    Bs[BUF][bk][bn+4] = tf32r(rb1.x); Bs[BUF][bk][bn+5] = tf32r(rb1.y);         \
    Bs[BUF][bk][bn+6] = tf32r(rb1.z); Bs[BUF][bk][bn+7] = tf32r(rb1.w);         \
} while (0)

    LDG_H(0);
    STS_H(0);
    __syncthreads();

    for (int it = 0; it < NSG; ++it) {
        int cur = it & 1;
        if (it + 1 < NSG) LDG_H((it + 1) * 16);

        uint32_t as_base = sptr(&As[cur][0][0]);
        #pragma unroll
        for (int kk = 0; kk < 16; kk += 8) {
            uint32_t afr[4][4], bfr[4][2];
            #pragma unroll
            for (int mt = 0; mt < 4; mt++) {
                uint32_t ad = as_base + (uint32_t)(((wm * 64 + mt * 16) * 20 + kk) * 4) + lmoff;
                ldsm_x4(afr[mt][0], afr[mt][1], afr[mt][2], afr[mt][3], ad);
            }
            #pragma unroll
            for (int nt = 0; nt < 4; nt++) {
                int cN = wn * 32 + nt * 8 + (lane >> 2);
                bfr[nt][0] = fu(Bs[cur][kk     + (lane & 3)][cN]);
                bfr[nt][1] = fu(Bs[cur][kk + 4 + (lane & 3)][cN]);
            }
            #pragma unroll
            for (int mt = 0; mt < 4; mt++)
                #pragma unroll
                for (int nt = 0; nt < 4; nt++)
                    MMA_TF32(acc[mt][nt], afr[mt], bfr[nt]);
        }
        if (it + 1 < NSG) { STS_H(cur ^ 1); __syncthreads(); }
    }
#undef LDG_H
#undef STS_H

    size_t ob = ((size_t)mp * BB + m0) * D;
    #pragma unroll
    for (int mt = 0; mt < 4; mt++) {
        int r = wm * 64 + mt * 16 + (lane >> 2);
        #pragma unroll
        for (int nt = 0; nt < 4; nt++) {
            int c = wn * 32 + nt * 8 + 2 * (lane & 3);
            float2 v0, v1;
            v0.x = fmaxf(acc[mt][nt][0], 0.f); v0.y = fmaxf(acc[mt][nt][1], 0.f);
            v1.x = fmaxf(acc[mt][nt][2], 0.f); v1.y = fmaxf(acc[mt][nt][3], 0.f);
            *(float2*)(g_h0 + ob + (size_t)r       * D + c) = v0;
            *(float2*)(g_h0 + ob + (size_t)(r + 8) * D + c) = v1;
        }
    }
}

// ---------------- small node GEMM MODE 2 (cp.async NS=6 ring): serial tail ----------------
__global__ __launch_bounds__(256) void gemm_h_small2(const float* __restrict__ W_self,
                                                     const float* __restrict__ W_neigh) {
    constexpr int KTOT = D + DE;
    constexpr int NSG  = KTOT / 16;       // 18
    constexpr int NS   = 6;
    int mp = blockIdx.y;
    int m0 = blockIdx.x * 128;

    extern __shared__ float dsm[];
    float* Asd = dsm;                     // [NS][128][20]
    float* Bsd = dsm + NS * 128 * 20;     // [NS][16][136]
#define AS(b,r,k) Asd[((b)*128 + (r))*20 + (k)]
#define BS(b,k,n) Bsd[((b)*16  + (k))*136 + (n)]

    int tid  = threadIdx.x;
    int lane = tid & 31;
    int w    = tid >> 5;
    int wm   = w >> 2;
    int wn   = w & 3;
    int ar   = tid >> 1;
    int kq   = (tid & 1) * 8;
    int bk   = tid >> 4;
    int bn   = (tid & 15) * 8;
    int row16 = lane & 15;
    int sel4  = (lane >> 4) * 4;
    uint32_t lmoff = (uint32_t)((row16 * 20 + sel4) * 4);

    const float* H0p = g_h0    + ((size_t)mp * BB + m0) * D;
    const float* P2p = g_ninL1 + ((size_t)mp * BB + m0) * DE;
    const float* Wsp = W_self  + ((long)(mp * 2 + 1)) * D  * D;
    const float* Wnp = W_neigh + ((long)(mp * 2 + 1)) * DE * D;

    float acc[4][4][4];
    #pragma unroll
    for (int i = 0; i < 4; i++)
        #pragma unroll
        for (int j = 0; j < 4; j++)
            #pragma unroll
            for (int q = 0; q < 4; q++) acc[i][j][q] = 0.f;

#define ISSUE_SM(SS) do {                                                       \
    int _s = (SS);                                                              \
    if (_s < NSG) {                                                             \
        int _k = _s * 16;                                                       \
        int _b = _s % NS;                                                       \
        const float* ap = (_k < D) ? H0p + (long)ar * D + _k                    \
                                   : P2p + (long)ar * DE + (_k - D);            \
        uint32_t da = sptr(&AS(_b, ar, kq));                                    \
        CP16(da,      ap + kq);                                                 \
        CP16(da + 16, ap + kq + 4);                                             \
        const float* wrow = (_k < D) ? (Wsp + (long)(_k + bk) * D)              \
                                     : (Wnp + (long)(_k - D + bk) * D);         \
        uint32_t db = sptr(&BS(_b, bk, bn));                                    \
        CP16(db,      wrow + bn);                                               \
        CP16(db + 16, wrow + bn + 4);                                           \
    }                                                                           \
    CP_COMMIT;                                                                  \
} while (0)

    ISSUE_SM(0); ISSUE_SM(1); ISSUE_SM(2); ISSUE_SM(3); ISSUE_SM(4);

    for (int it = 0; it < NSG; ++it) {
        CP_WAIT(NS - 2);
        __syncthreads();
        ISSUE_SM(it + NS - 1);

        int cur = it % NS;
        uint32_t as_base = sptr(&AS(cur, 0, 0));
        #pragma unroll
        for (int kk = 0; kk < 16; kk += 8) {
            uint32_t afr[4][4], bfr[4][2];
            #pragma unroll
            for (int mt = 0; mt < 4; mt++) {
                uint32_t ad = as_base + (uint32_t)(((wm * 64 + mt * 16) * 20 + kk) * 4) + lmoff;
                ldsm_x4(afr[mt][0], afr[mt][1], afr[mt][2], afr[mt][3], ad);
                afr[mt][0] = cvt_frag(afr[mt][0]);
                afr[mt][1] = cvt_frag(afr[mt][1]);
                afr[mt][2] = cvt_frag(afr[mt][2]);
                afr[mt][3] = cvt_frag(afr[mt][3]);
            }
            #pragma unroll
            for (int nt = 0; nt < 4; nt++) {
                int cN = wn * 32 + nt * 8 + (lane >> 2);
                bfr[nt][0] = cvt_frag(fu(BS(cur, kk     + (lane & 3), cN)));
                bfr[nt][1] = cvt_frag(fu(BS(cur, kk + 4 + (lane & 3), cN)));
            }
            #pragma unroll
            for (int mt = 0; mt < 4; mt++)
                #pragma unroll
                for (int nt = 0; nt < 4; nt++)
                    MMA_TF32(acc[mt][nt], afr[mt], bfr[nt]);
        }
        __syncthreads();
    }
#undef ISSUE_SM
#undef AS
#undef BS

    size_t ob = ((size_t)mp * BB + m0) * D;
    #pragma unroll
    for (int mt = 0; mt < 4; mt++) {
        int r = wm * 64 + mt * 16 + (lane >> 2);
        #pragma unroll
        for (int nt = 0; nt < 4; nt++) {
            int c = wn * 32 + nt * 8 + 2 * (lane & 3);
            float2 v0, v1;
            v0.x = fmaxf(acc[mt][nt][0], 0.f); v0.y = fmaxf(acc[mt][nt][1], 0.f);
            v1.x = fmaxf(acc[mt][nt][2], 0.f); v1.y = fmaxf(acc[mt][nt][3], 0.f);
            *(float2*)(g_outs + ob + (size_t)r       * D + c) = v0;
            *(float2*)(g_outs + ob + (size_t)(r + 8) * D + c) = v1;
        }
    }
}

// ---------------- final fuse: warp-per-row, shuffle-only reductions ----------------
__global__ __launch_bounds__(256) void k_fuse(const float* __restrict__ attn,
                                              const float* __restrict__ fc_w,
                                              const float* __restrict__ fc_b,
                                              float* __restrict__ out) {
    __shared__ float sfw[D * NC];
    int tid = threadIdx.x;
    for (int i = tid; i < D * NC; i += 256) sfw[i] = fc_w[i];
    __syncthreads();

    int warp = tid >> 5, lane = tid & 31;
    int b = blockIdx.x * 8 + warp;
    int d0 = lane * 4;

    float4 v0 = *(const float4*)&g_outs[((size_t)0 * BB + b) * D + d0];
    float4 v1 = *(const float4*)&g_outs[((size_t)1 * BB + b) * D + d0];
    float4 v2 = *(const float4*)&g_outs[((size_t)2 * BB + b) * D + d0];
    float4 a  = *(const float4*)&attn[d0];

    float s0 = wred(v0.x*a.x + v0.y*a.y + v0.z*a.z + v0.w*a.w);
    float s1 = wred(v1.x*a.x + v1.y*a.y + v1.z*a.z + v1.w*a.w);
    float s2 = wred(v2.x*a.x + v2.y*a.y + v2.z*a.z + v2.w*a.w);
    s0 = tanhf(s0); s1 = tanhf(s1); s2 = tanhf(s2);
    float mx = fmaxf(s0, fmaxf(s1, s2));
    float e0 = expf(s0 - mx), e1 = expf(s1 - mx), e2 = expf(s2 - mx);
    float inv = 1.f / (e0 + e1 + e2);

    float em[4];
    em[0] = (e0*v0.x + e1*v1.x + e2*v2.x) * inv;
    em[1] = (e0*v0.y + e1*v1.y + e2*v2.y) * inv;
    em[2] = (e0*v0.z + e1*v1.z + e2*v2.z) * inv;
    em[3] = (e0*v0.w + e1*v1.w + e2*v2.w) * inv;

    float n2 = wred(em[0]*em[0] + em[1]*em[1] + em[2]*em[2] + em[3]*em[3]);
    float rn = 1.f / fmaxf(sqrtf(n2), 1e-12f);
    em[0] *= rn; em[1] *= rn; em[2] *= rn; em[3] *= rn;

    #pragma unroll
    for (int nc = 0; nc < NC; nc++) {
        float p = em[0] * sfw[(d0+0)*NC + nc] + em[1] * sfw[(d0+1)*NC + nc]
                + em[2] * sfw[(d0+2)*NC + nc] + em[3] * sfw[(d0+3)*NC + nc];
        p = wred(p);
        if (lane == 0) out[b * NC + nc] = p + fc_b[nc];
    }
}

// ---------------- launch ----------------
extern "C" void kernel_launch(void* const* d_in, const int* in_sizes, int n_in,
                              void* d_out, int out_size) {
    (void)in_sizes; (void)n_in; (void)out_size;
    const int*   ids       = (const int*)  d_in[0];
    const float* feats     = (const float*)d_in[1];
    const float* edge_emb  = (const float*)d_in[2];
    const int*   adj_nodes = (const int*)  d_in[3];
    const int*   adj_edges = (const int*)  d_in[4];
    const float* W_self    = (const float*)d_in[5];
    const float* W_neigh   = (const float*)d_in[6];
    const float* W_edge    = (const float*)d_in[7];
    const float* attn      = (const float*)d_in[8];
    const float* fc_w      = (const float*)d_in[9];
    const float* fc_b      = (const float*)d_in[10];
    float* out = (float*)d_out;

    const int SMEM_G0 = 4 * 2 * H16SLAB * 2;             // 49152 (NS=4, fp16 slabs)
    const int SMEM_SM2 = 6 * (128 * 20 + 16 * 136) * 4;  // 113664 (tail GEMM NS=6 ring)
    static cudaStream_t s1 = nullptr;
    static cudaEvent_t  evA = nullptr, evB = nullptr;
    if (!s1) {
        cudaFuncSetAttribute(gemm_h0, cudaFuncAttributeMaxDynamicSharedMemorySize, SMEM_G0);
        cudaFuncSetAttribute(gemm_h_small2, cudaFuncAttributeMaxDynamicSharedMemorySize, SMEM_SM2);
        cudaStreamCreateWithFlags(&s1, cudaStreamNonBlocking);
        cudaEventCreateWithFlags(&evA, cudaEventDisableTiming);
        cudaEventCreateWithFlags(&evB, cudaEventDisableTiming);
    }

    // default-stream prefix: merged weight-round + idx
    k_prep0<<<(NMP*2*288*128 + 255) / 256, 256>>>(ids, adj_nodes, adj_edges,
                                                  W_self, W_neigh, W_edge);
    cudaEventRecord(evA, 0);

    // side chain (under hop2): hop1 mean, ee pack, h0 GEMM (R13-proven LDG/STS path)
    cudaStreamWaitEvent(s1, evA, 0);
    k_mean_hop1<<<NMP * BB / 8, 256, 0, s1>>>(feats, edge_emb);
    k_pack_e<<<NMP * M1 / 8, 256, 0, s1>>>(edge_emb);
    gemm_h_small1<<<dim3(BB / 128, NMP), 256, 0, s1>>>(feats, ids, W_self, W_neigh);
    cudaEventRecord(evB, s1);

    // main chain
    k_mean_hop2<<<NMP * M1 / 8, 256>>>(feats, edge_emb, adj_nodes, adj_edges);
    gemm_h0<<<dim3(128, NMP), 256, SMEM_G0>>>();
    cudaStreamWaitEvent(0, evB, 0);
    gemm_edge<<<dim3(128, NMP), 256>>>();
    gemm_h_small2<<<dim3(BB / 128, NMP), 256, SMEM_SM2>>>(W_self, W_neigh);
    k_fuse<<<BB / 8, 256>>>(attn, fc_w, fc_b, out);
}